// round 1
// baseline (speedup 1.0000x reference)
#include <cuda_runtime.h>
#include <math.h>

#define BATCH 4
#define CDIM  64
#define HH    256
#define WW    256
#define HWD   65536          // H*W
#define CHROWS 16384         // C*H
#define HID   170
#define HID2  340

// ---------------- scratch (device globals; no allocations allowed) ----------------
__device__ float g_bufA[(size_t)BATCH * CDIM * HWD];   // LN output / AV output (reused)
__device__ float g_bufM[(size_t)BATCH * CDIM * HWD];   // wxw block output (m)
__device__ float g_bufZ[(size_t)BATCH * CDIM * HWD];   // hxh block output (z)
__device__ float g_qkv1[(size_t)BATCH * HID2 * HWD];   // pre-dwconv qkv / ffn hidden / gate out
__device__ float g_qkv2[(size_t)BATCH * HID2 * HWD];   // post-dwconv qkv / ffn hidden
__device__ float g_attn[(size_t)BATCH * WW * WW];      // attention logits/probs
__device__ float g_invq[BATCH * CHROWS];
__device__ float g_invk[BATCH * CHROWS];
__device__ float g_sq[BATCH * HH];
__device__ float g_sk[BATCH * HH];

// ---------------- LayerNorm over channel dim (per pixel) ----------------
__global__ void ln_kernel(const float* __restrict__ x, const float* __restrict__ w,
                          const float* __restrict__ b, float* __restrict__ y)
{
    long p = (long)blockIdx.x * blockDim.x + threadIdx.x;
    if (p >= (long)BATCH * HWD) return;
    int bb  = (int)(p >> 16);
    int pix = (int)(p & (HWD - 1));
    const float* xp = x + (long)bb * CDIM * HWD + pix;
    float s = 0.f, s2 = 0.f;
#pragma unroll
    for (int c = 0; c < CDIM; c++) {
        float v = xp[(long)c * HWD];
        s += v; s2 += v * v;
    }
    float mu  = s * (1.0f / CDIM);
    float var = s2 * (1.0f / CDIM) - mu * mu;
    float inv = rsqrtf(var + 1e-5f);
    float* yp = y + (long)bb * CDIM * HWD + pix;
#pragma unroll
    for (int c = 0; c < CDIM; c++) {
        float v = xp[(long)c * HWD];
        yp[(long)c * HWD] = (v - mu) * inv * w[c] + b[c];
    }
}

// ---------------- depthwise 3x3 conv, SAME zero padding ----------------
__global__ void dwconv_kernel(const float* __restrict__ x, const float* __restrict__ wt,
                              const float* __restrict__ bias, float* __restrict__ y, int OC)
{
    long idx = (long)blockIdx.x * blockDim.x + threadIdx.x;
    long total = (long)BATCH * OC * HWD;
    if (idx >= total) return;
    int wcol = (int)(idx & (WW - 1));
    int h    = (int)((idx >> 8) & (HH - 1));
    long bc  = idx >> 16;                   // b*OC + c
    int c    = (int)(bc % OC);
    const float* xp = x + (bc << 16);
    float acc = bias[c];
#pragma unroll
    for (int kh = -1; kh <= 1; kh++) {
        int hh = h + kh;
        if (hh < 0 || hh >= HH) continue;
#pragma unroll
        for (int kw = -1; kw <= 1; kw++) {
            int wc = wcol + kw;
            if (wc < 0 || wc >= WW) continue;
            acc += wt[c * 9 + (kh + 1) * 3 + (kw + 1)] * xp[hh * WW + wc];
        }
    }
    y[idx] = acc;
}

// ---------------- per-row inverse L2 norm (rows of length 256, contiguous) ----------------
__global__ void rowinv_kernel(const float* __restrict__ src, long sBatch, float* __restrict__ inv)
{
    int warp = threadIdx.x >> 5, lane = threadIdx.x & 31;
    int row = blockIdx.x * 8 + warp;        // 0..CHROWS-1
    int b = blockIdx.y;
    const float* p = src + (long)b * sBatch + (long)row * WW;
    float s = 0.f;
#pragma unroll
    for (int i = 0; i < 8; i++) { float v = p[lane + i * 32]; s += v * v; }
#pragma unroll
    for (int o = 16; o > 0; o >>= 1) s += __shfl_down_sync(0xffffffffu, s, o);
    if (lane == 0) inv[b * CHROWS + row] = 1.f / fmaxf(sqrtf(s), 1e-12f);
}

// ---------------- hxh inverse norm: per (b,h) over (c,w) ----------------
__global__ void hnorm_kernel(const float* __restrict__ src, float* __restrict__ out)
{
    int b = blockIdx.y, h = blockIdx.x;
    int t = threadIdx.x;   // 256 = w
    const float* p = src + (long)b * (3 * CDIM) * HWD + (long)h * WW + t;
    float s = 0.f;
#pragma unroll
    for (int c = 0; c < CDIM; c++) { float v = p[(long)c * HWD]; s += v * v; }
    __shared__ float red[256];
    red[t] = s; __syncthreads();
    for (int o = 128; o > 0; o >>= 1) { if (t < o) red[t] += red[t + o]; __syncthreads(); }
    if (t == 0) out[b * HH + h] = 1.f / fmaxf(sqrtf(red[0]), 1e-12f);
}

// ---------------- softmax over last dim of [B, 256, 256] ----------------
__global__ void softmax_kernel(float* __restrict__ attn, const float* __restrict__ temp,
                               const float* __restrict__ sq, const float* __restrict__ sk)
{
    int b = blockIdx.y;
    int r = blockIdx.x;
    float* row = attn + ((long)b * WW + r) * WW;
    int t = threadIdx.x;  // 256
    float v = row[t] * temp[0];
    if (sq) v *= sq[b * WW + r] * sk[b * WW + t];
    __shared__ float red[256];
    red[t] = v; __syncthreads();
    for (int o = 128; o > 0; o >>= 1) { if (t < o) red[t] = fmaxf(red[t], red[t + o]); __syncthreads(); }
    float mx = red[0]; __syncthreads();
    float e = __expf(v - mx);
    red[t] = e; __syncthreads();
    for (int o = 128; o > 0; o >>= 1) { if (t < o) red[t] += red[t + o]; __syncthreads(); }
    row[t] = e * (1.f / red[0]);
}

// ---------------- GELU(exact) gate: g = gelu(x1) * x2 ----------------
__global__ void gate_kernel(const float* __restrict__ t, float* __restrict__ g)
{
    long idx = (long)blockIdx.x * blockDim.x + threadIdx.x;
    long total = (long)BATCH * HID * HWD;
    if (idx >= total) return;
    int b = (int)(idx / ((long)HID * HWD));
    long rem = idx - (long)b * HID * HWD;
    const float* base = t + (long)b * HID2 * HWD;
    float x1 = base[rem];
    float x2 = base[(long)HID * HWD + rem];
    float ge = 0.5f * x1 * (1.0f + erff(x1 * 0.70710678118654752f));
    g[idx] = ge * x2;
}

// ---------------- generic tiled GEMM ----------------
// C[m,n] (+)= sum_k A(m,k) * B(k,n)   with optional per-k scales folded into loads.
// TA=0: A[m*lda+k]  TA=1: A[k*lda+m]
// TB=0: B[k*ldb+n]  TB=1: B[n*ldb+k]
// batch z: zb=z/ksplit (k-split index ks=z%ksplit), z1=zb/zdiv, z2=zb%zdiv;
// pointer offsets = z1*s?1 + z2*s?2.
template<int TA, int TB>
__global__ void gemm_kernel(
    const float* __restrict__ A, const float* __restrict__ B, float* __restrict__ C,
    int M, int N, int K, int lda, int ldb, int ldc,
    int ksplit, int zdiv,
    long sA1, long sA2, long sB1, long sB2, long sC1, long sC2,
    const float* __restrict__ bias,
    const float* __restrict__ res, long sR1, long sR2,
    const float* __restrict__ ksA, long sKA1,
    const float* __restrict__ ksB, long sKB1,
    int atomic_out)
{
    const int BM = 64, BN = 64, BK = 16;
    __shared__ __align__(16) float As[BK][BM + 4];
    __shared__ __align__(16) float Bs[BK][BN + 4];

    int z  = blockIdx.z;
    int zb = z / ksplit;
    int ks = z - zb * ksplit;
    int z1 = zb / zdiv, z2 = zb - z1 * zdiv;
    const float* Ap = A + (long)z1 * sA1 + (long)z2 * sA2;
    const float* Bp = B + (long)z1 * sB1 + (long)z2 * sB2;
    float*       Cp = C + (long)z1 * sC1 + (long)z2 * sC2;
    const float* ksAp = ksA ? ksA + (long)z1 * sKA1 : nullptr;
    const float* ksBp = ksB ? ksB + (long)z1 * sKB1 : nullptr;

    int m0 = blockIdx.x * BM;
    int n0 = blockIdx.y * BN;

    int kchunk = (K + ksplit - 1) / ksplit;
    int kbeg = ks * kchunk;
    int kend = min(K, kbeg + kchunk);

    int tid = threadIdx.x;
    int tx = tid & 15, ty = tid >> 4;

    float acc[4][4];
#pragma unroll
    for (int i = 0; i < 4; i++)
#pragma unroll
        for (int j = 0; j < 4; j++) acc[i][j] = 0.f;

    for (int k0 = kbeg; k0 < kend; k0 += BK) {
        if (TA == 0) {
            int m  = tid >> 2;
            int kk = (tid & 3) * 4;
#pragma unroll
            for (int j = 0; j < 4; j++) {
                int kg = k0 + kk + j;
                float v = 0.f;
                if (m0 + m < M && kg < kend) v = Ap[(long)(m0 + m) * lda + kg];
                if (ksAp && kg < kend) v *= ksAp[kg];
                As[kk + j][m] = v;
            }
        } else {
            int kk = tid >> 4;
            int m  = (tid & 15) * 4;
#pragma unroll
            for (int j = 0; j < 4; j++) {
                int kg = k0 + kk;
                float v = 0.f;
                if (kg < kend && m0 + m + j < M) v = Ap[(long)kg * lda + m0 + m + j];
                if (ksAp && kg < kend) v *= ksAp[kg];
                As[kk][m + j] = v;
            }
        }
        if (TB == 0) {
            int kk = tid >> 4;
            int n  = (tid & 15) * 4;
#pragma unroll
            for (int j = 0; j < 4; j++) {
                int kg = k0 + kk;
                float v = 0.f;
                if (kg < kend) v = Bp[(long)kg * ldb + n0 + n + j];
                if (ksBp && kg < kend) v *= ksBp[kg];
                Bs[kk][n + j] = v;
            }
        } else {
            int n  = tid >> 2;
            int kk = (tid & 3) * 4;
#pragma unroll
            for (int j = 0; j < 4; j++) {
                int kg = k0 + kk + j;
                float v = 0.f;
                if (kg < kend) v = Bp[(long)(n0 + n) * ldb + kg];
                if (ksBp && kg < kend) v *= ksBp[kg];
                Bs[kk + j][n] = v;
            }
        }
        __syncthreads();
#pragma unroll
        for (int kk = 0; kk < BK; kk++) {
            float4 av = *reinterpret_cast<const float4*>(&As[kk][ty * 4]);
            float4 bv = *reinterpret_cast<const float4*>(&Bs[kk][tx * 4]);
            float a[4] = {av.x, av.y, av.z, av.w};
            float b[4] = {bv.x, bv.y, bv.z, bv.w};
#pragma unroll
            for (int i = 0; i < 4; i++)
#pragma unroll
                for (int j = 0; j < 4; j++)
                    acc[i][j] = fmaf(a[i], b[j], acc[i][j]);
        }
        __syncthreads();
    }

    const float* Rp = res ? res + (long)z1 * sR1 + (long)z2 * sR2 : nullptr;
#pragma unroll
    for (int i = 0; i < 4; i++) {
        int m = m0 + ty * 4 + i;
        if (m >= M) continue;
        float bvv = bias ? bias[m] : 0.f;
#pragma unroll
        for (int j = 0; j < 4; j++) {
            int n = n0 + tx * 4 + j;
            long off = (long)m * ldc + n;
            float v = acc[i][j] + bvv;
            if (Rp) v += Rp[off];
            if (atomic_out) atomicAdd(&Cp[off], v);
            else Cp[off] = v;
        }
    }
}

// ---------------- host helper ----------------
static void gemm_launch(int TA, int TB, dim3 grid,
    const float* A, const float* B, float* C,
    int M, int N, int K, int lda, int ldb, int ldc,
    int ksplit, int zdiv,
    long sA1, long sA2, long sB1, long sB2, long sC1, long sC2,
    const float* bias, const float* res, long sR1, long sR2,
    const float* ksA, long sKA1, const float* ksB, long sKB1, int atomic_out)
{
    if (TA == 0 && TB == 0)
        gemm_kernel<0,0><<<grid, 256>>>(A,B,C,M,N,K,lda,ldb,ldc,ksplit,zdiv,
            sA1,sA2,sB1,sB2,sC1,sC2,bias,res,sR1,sR2,ksA,sKA1,ksB,sKB1,atomic_out);
    else if (TA == 1)
        gemm_kernel<1,0><<<grid, 256>>>(A,B,C,M,N,K,lda,ldb,ldc,ksplit,zdiv,
            sA1,sA2,sB1,sB2,sC1,sC2,bias,res,sR1,sR2,ksA,sKA1,ksB,sKB1,atomic_out);
    else
        gemm_kernel<0,1><<<grid, 256>>>(A,B,C,M,N,K,lda,ldb,ldc,ksplit,zdiv,
            sA1,sA2,sB1,sB2,sC1,sC2,bias,res,sR1,sR2,ksA,sKA1,ksB,sKB1,atomic_out);
}

extern "C" void kernel_launch(void* const* d_in, const int* in_sizes, int n_in,
                              void* d_out, int out_size)
{
    const float* x        = (const float*)d_in[0];
    // d_in[1] = zero_map (unused)
    const float* w_ln_w   = (const float*)d_in[2];
    const float* w_ln_b   = (const float*)d_in[3];
    const float* w_qkv_w  = (const float*)d_in[4];
    const float* w_qkv_b  = (const float*)d_in[5];
    const float* w_dw_w   = (const float*)d_in[6];
    const float* w_dw_b   = (const float*)d_in[7];
    const float* w_proj_w = (const float*)d_in[8];
    const float* w_proj_b = (const float*)d_in[9];
    const float* w_temp   = (const float*)d_in[10];
    const float* h_ln_w   = (const float*)d_in[11];
    const float* h_ln_b   = (const float*)d_in[12];
    const float* h_qkv_w  = (const float*)d_in[13];
    const float* h_qkv_b  = (const float*)d_in[14];
    const float* h_dw_w   = (const float*)d_in[15];
    const float* h_dw_b   = (const float*)d_in[16];
    const float* h_proj_w = (const float*)d_in[17];
    const float* h_proj_b = (const float*)d_in[18];
    const float* h_temp   = (const float*)d_in[19];
    const float* n2_w     = (const float*)d_in[20];
    const float* n2_b     = (const float*)d_in[21];
    const float* ffn_in_w = (const float*)d_in[22];
    const float* ffn_in_b = (const float*)d_in[23];
    const float* ffn_dw_w = (const float*)d_in[24];
    const float* ffn_dw_b = (const float*)d_in[25];
    const float* ffn_out_w= (const float*)d_in[26];
    const float* ffn_out_b= (const float*)d_in[27];
    float* out = (float*)d_out;

    float *bufA, *bufM, *bufZ, *qkv1, *qkv2, *attn, *invq, *invk, *sq, *sk;
    cudaGetSymbolAddress((void**)&bufA, g_bufA);
    cudaGetSymbolAddress((void**)&bufM, g_bufM);
    cudaGetSymbolAddress((void**)&bufZ, g_bufZ);
    cudaGetSymbolAddress((void**)&qkv1, g_qkv1);
    cudaGetSymbolAddress((void**)&qkv2, g_qkv2);
    cudaGetSymbolAddress((void**)&attn, g_attn);
    cudaGetSymbolAddress((void**)&invq, g_invq);
    cudaGetSymbolAddress((void**)&invk, g_invk);
    cudaGetSymbolAddress((void**)&sq,   g_sq);
    cudaGetSymbolAddress((void**)&sk,   g_sk);

    const long sX  = (long)CDIM * HWD;   // per-batch stride of C=64 tensors
    const long sQ  = (long)3 * CDIM * HWD;
    const dim3 gPix((HWD / 64) , 1, 1);  // unused placeholder

    // ================= attention (WxW) =================
    ln_kernel<<<(BATCH * HWD) / 256, 256>>>(x, w_ln_w, w_ln_b, bufA);
    gemm_launch(0,0, dim3(3, HWD/64, BATCH), w_qkv_w, bufA, qkv1,
        192, HWD, 64, 64, HWD, HWD, 1, 1,
        0,0, sX,0, sQ,0, w_qkv_b, nullptr,0,0, nullptr,0, nullptr,0, 0);
    dwconv_kernel<<<((long)BATCH*192*HWD)/256, 256>>>(qkv1, w_dw_w, w_dw_b, qkv2, 192);
    rowinv_kernel<<<dim3(CHROWS/8, BATCH), 256>>>(qkv2,              sQ, invq);
    rowinv_kernel<<<dim3(CHROWS/8, BATCH), 256>>>(qkv2 + 64*(long)HWD, sQ, invk);
    cudaMemsetAsync(attn, 0, (size_t)BATCH * WW * WW * sizeof(float));
    // gram: attn[w,u] += sum_n qhat[n,w]*khat[n,u]  (TA=1, split-K=8)
    gemm_launch(1,0, dim3(4,4, BATCH*8), qkv2, qkv2 + 64*(long)HWD, attn,
        WW, WW, CHROWS, WW, WW, WW, 8, 1,
        sQ,0, sQ,0, (long)WW*WW,0, nullptr, nullptr,0,0,
        invq, CHROWS, invk, CHROWS, 1);
    softmax_kernel<<<dim3(WW, BATCH), 256>>>(attn, w_temp, nullptr, nullptr);
    // AV: out[(c,h),u] = sum_w v[(c,h),w]*attn[w,u]
    gemm_launch(0,0, dim3(CHROWS/64, 4, BATCH), qkv2 + 128*(long)HWD, attn, bufA,
        CHROWS, WW, WW, WW, WW, WW, 1, 1,
        sQ,0, (long)WW*WW,0, sX,0, nullptr, nullptr,0,0, nullptr,0, nullptr,0, 0);
    // proj + residual x -> bufM
    gemm_launch(0,0, dim3(1, HWD/64, BATCH), w_proj_w, bufA, bufM,
        64, HWD, 64, 64, HWD, HWD, 1, 1,
        0,0, sX,0, sX,0, w_proj_b, x, sX,0, nullptr,0, nullptr,0, 0);

    // ================= attention (HxH) =================
    ln_kernel<<<(BATCH * HWD) / 256, 256>>>(bufM, h_ln_w, h_ln_b, bufA);
    gemm_launch(0,0, dim3(3, HWD/64, BATCH), h_qkv_w, bufA, qkv1,
        192, HWD, 64, 64, HWD, HWD, 1, 1,
        0,0, sX,0, sQ,0, h_qkv_b, nullptr,0,0, nullptr,0, nullptr,0, 0);
    dwconv_kernel<<<((long)BATCH*192*HWD)/256, 256>>>(qkv1, h_dw_w, h_dw_b, qkv2, 192);
    hnorm_kernel<<<dim3(HH, BATCH), 256>>>(qkv2,               sq);
    hnorm_kernel<<<dim3(HH, BATCH), 256>>>(qkv2 + 64*(long)HWD, sk);
    cudaMemsetAsync(attn, 0, (size_t)BATCH * WW * WW * sizeof(float));
    // gram: attn[h,g] += sum_w q[c,h,w]*k[c,g,w], accumulated over c via atomics
    gemm_launch(0,1, dim3(4,4, BATCH*64), qkv2, qkv2 + 64*(long)HWD, attn,
        HH, HH, WW, WW, WW, WW, 1, 64,
        sQ,(long)HWD, sQ,(long)HWD, (long)WW*WW,0, nullptr, nullptr,0,0,
        nullptr,0, nullptr,0, 1);
    softmax_kernel<<<dim3(WW, BATCH), 256>>>(attn, h_temp, sq, sk);
    // AV: out[c][h,w] = sum_g attn[h,g]*v[c][g,w]
    gemm_launch(0,0, dim3(4,4, BATCH*64), attn, qkv2 + 128*(long)HWD, bufA,
        HH, WW, HH, WW, WW, WW, 1, 64,
        (long)WW*WW,0, sQ,(long)HWD, sX,(long)HWD, nullptr, nullptr,0,0,
        nullptr,0, nullptr,0, 0);
    // proj + residual m -> bufZ
    gemm_launch(0,0, dim3(1, HWD/64, BATCH), h_proj_w, bufA, bufZ,
        64, HWD, 64, 64, HWD, HWD, 1, 1,
        0,0, sX,0, sX,0, h_proj_b, bufM, sX,0, nullptr,0, nullptr,0, 0);

    // ================= FFN =================
    ln_kernel<<<(BATCH * HWD) / 256, 256>>>(bufZ, n2_w, n2_b, bufA);
    gemm_launch(0,0, dim3((HID2+63)/64, HWD/64, BATCH), ffn_in_w, bufA, qkv1,
        HID2, HWD, 64, 64, HWD, HWD, 1, 1,
        0,0, sX,0, (long)HID2*HWD,0, ffn_in_b, nullptr,0,0, nullptr,0, nullptr,0, 0);
    dwconv_kernel<<<((long)BATCH*HID2*HWD)/256, 256>>>(qkv1, ffn_dw_w, ffn_dw_b, qkv2, HID2);
    gate_kernel<<<((long)BATCH*HID*HWD + 255)/256, 256>>>(qkv2, qkv1);
    // out = ffn_out(gated) + bias + z
    gemm_launch(0,0, dim3(1, HWD/64, BATCH), ffn_out_w, qkv1, out,
        64, HWD, HID, HID, HWD, HWD, 1, 1,
        0,0, (long)HID*HWD,0, sX,0, ffn_out_b, bufZ, sX,0, nullptr,0, nullptr,0, 0);
}

// round 2
// speedup vs baseline: 1.4948x; 1.4948x over previous
#include <cuda_runtime.h>
#include <math.h>

#define BATCH 4
#define CDIM  64
#define HH    256
#define WW    256
#define HWD   65536          // H*W
#define CHROWS 16384         // C*H
#define HID   170
#define HID2  340

// ---------------- scratch (device globals; no allocations allowed) ----------------
__device__ float g_bufA[(size_t)BATCH * CDIM * HWD];
__device__ float g_bufM[(size_t)BATCH * CDIM * HWD];
__device__ float g_bufZ[(size_t)BATCH * CDIM * HWD];
__device__ float g_qkv1[(size_t)BATCH * HID2 * HWD];
__device__ float g_qkv2[(size_t)BATCH * HID2 * HWD];
__device__ float g_attn[(size_t)BATCH * WW * WW];
__device__ float g_invq[BATCH * CHROWS];
__device__ float g_invk[BATCH * CHROWS];
__device__ float g_sq[BATCH * HH];
__device__ float g_sk[BATCH * HH];

// ---------------- helpers ----------------
__device__ __forceinline__ float tf32r(float v) {
    unsigned u;
    asm("cvt.rna.tf32.f32 %0, %1;" : "=r"(u) : "f"(v));
    return __uint_as_float(u);
}
__device__ __forceinline__ void mma8(float* d, unsigned a0, unsigned a1, unsigned a2, unsigned a3,
                                     unsigned b0, unsigned b1) {
    asm volatile(
        "mma.sync.aligned.m16n8k8.row.col.f32.tf32.tf32.f32 "
        "{%0,%1,%2,%3},{%4,%5,%6,%7},{%8,%9},{%0,%1,%2,%3};\n"
        : "+f"(d[0]), "+f"(d[1]), "+f"(d[2]), "+f"(d[3])
        : "r"(a0), "r"(a1), "r"(a2), "r"(a3), "r"(b0), "r"(b1));
}

// ---------------- LayerNorm over channel dim (per pixel) ----------------
__global__ void ln_kernel(const float* __restrict__ x, const float* __restrict__ w,
                          const float* __restrict__ b, float* __restrict__ y)
{
    long p = (long)blockIdx.x * blockDim.x + threadIdx.x;
    if (p >= (long)BATCH * HWD) return;
    int bb  = (int)(p >> 16);
    int pix = (int)(p & (HWD - 1));
    const float* xp = x + (long)bb * CDIM * HWD + pix;
    float s = 0.f, s2 = 0.f;
#pragma unroll
    for (int c = 0; c < CDIM; c++) {
        float v = xp[(long)c * HWD];
        s += v; s2 += v * v;
    }
    float mu  = s * (1.0f / CDIM);
    float var = s2 * (1.0f / CDIM) - mu * mu;
    float inv = rsqrtf(var + 1e-5f);
    float* yp = y + (long)bb * CDIM * HWD + pix;
#pragma unroll
    for (int c = 0; c < CDIM; c++) {
        float v = xp[(long)c * HWD];
        yp[(long)c * HWD] = (v - mu) * inv * w[c] + b[c];
    }
}

// ---------------- depthwise 3x3 conv, SAME, 4 outputs per thread ----------------
__global__ void dwconv4_kernel(const float* __restrict__ x, const float* __restrict__ wt,
                               const float* __restrict__ bias, float* __restrict__ y, int OC)
{
    long idx = (long)blockIdx.x * blockDim.x + threadIdx.x;
    long total = (long)BATCH * OC * (HWD / 4);
    if (idx >= total) return;
    int w4 = (int)(idx & 63) * 4;
    int h  = (int)((idx >> 6) & 255);
    long bc = idx >> 14;
    int c = (int)(bc % OC);
    const float* xp = x + (bc << 16);
    float b0 = bias[c];
    float acc0 = b0, acc1 = b0, acc2 = b0, acc3 = b0;
#pragma unroll
    for (int kh = -1; kh <= 1; kh++) {
        int hh = h + kh;
        if (hh < 0 || hh >= HH) continue;
        const float* row = xp + hh * WW;
        float vm1 = (w4 > 0)       ? row[w4 - 1] : 0.f;
        float4 v  = *reinterpret_cast<const float4*>(&row[w4]);
        float vp4 = (w4 + 4 < WW)  ? row[w4 + 4] : 0.f;
        float vals[6] = {vm1, v.x, v.y, v.z, v.w, vp4};
        const float* wr = wt + c * 9 + (kh + 1) * 3;
#pragma unroll
        for (int kw = 0; kw < 3; kw++) {
            float g = wr[kw];
            acc0 = fmaf(g, vals[kw + 0], acc0);
            acc1 = fmaf(g, vals[kw + 1], acc1);
            acc2 = fmaf(g, vals[kw + 2], acc2);
            acc3 = fmaf(g, vals[kw + 3], acc3);
        }
    }
    *reinterpret_cast<float4*>(&y[idx * 4]) = make_float4(acc0, acc1, acc2, acc3);
}

// ---------------- per-row inverse L2 norm (rows of length 256, contiguous) ----------------
__global__ void rowinv_kernel(const float* __restrict__ src, long sBatch, float* __restrict__ inv)
{
    int warp = threadIdx.x >> 5, lane = threadIdx.x & 31;
    int row = blockIdx.x * 8 + warp;
    int b = blockIdx.y;
    const float* p = src + (long)b * sBatch + (long)row * WW;
    float s = 0.f;
#pragma unroll
    for (int i = 0; i < 8; i++) { float v = p[lane + i * 32]; s += v * v; }
#pragma unroll
    for (int o = 16; o > 0; o >>= 1) s += __shfl_down_sync(0xffffffffu, s, o);
    if (lane == 0) inv[b * CHROWS + row] = 1.f / fmaxf(sqrtf(s), 1e-12f);
}

// ---------------- hxh inverse norm: per (b,h) over (c,w) ----------------
__global__ void hnorm_kernel(const float* __restrict__ src, float* __restrict__ out)
{
    int b = blockIdx.y, h = blockIdx.x;
    int t = threadIdx.x;
    const float* p = src + (long)b * (3 * CDIM) * HWD + (long)h * WW + t;
    float s = 0.f;
#pragma unroll
    for (int c = 0; c < CDIM; c++) { float v = p[(long)c * HWD]; s += v * v; }
    __shared__ float red[256];
    red[t] = s; __syncthreads();
    for (int o = 128; o > 0; o >>= 1) { if (t < o) red[t] += red[t + o]; __syncthreads(); }
    if (t == 0) out[b * HH + h] = 1.f / fmaxf(sqrtf(red[0]), 1e-12f);
}

// ---------------- softmax over last dim of [B, 256, 256] ----------------
__global__ void softmax_kernel(float* __restrict__ attn, const float* __restrict__ temp,
                               const float* __restrict__ sq, const float* __restrict__ sk)
{
    int b = blockIdx.y;
    int r = blockIdx.x;
    float* row = attn + ((long)b * WW + r) * WW;
    int t = threadIdx.x;
    float v = row[t] * temp[0];
    if (sq) v *= sq[b * WW + r] * sk[b * WW + t];
    __shared__ float red[256];
    red[t] = v; __syncthreads();
    for (int o = 128; o > 0; o >>= 1) { if (t < o) red[t] = fmaxf(red[t], red[t + o]); __syncthreads(); }
    float mx = red[0]; __syncthreads();
    float e = __expf(v - mx);
    red[t] = e; __syncthreads();
    for (int o = 128; o > 0; o >>= 1) { if (t < o) red[t] += red[t + o]; __syncthreads(); }
    row[t] = e * (1.f / red[0]);
}

// ---------------- GELU(exact) gate, vectorized ----------------
__global__ void gate4_kernel(const float* __restrict__ t, float* __restrict__ g)
{
    long idx = (long)blockIdx.x * blockDim.x + threadIdx.x;
    long total = (long)BATCH * HID * HWD / 4;
    if (idx >= total) return;
    long e = idx * 4;
    int b = (int)(e / ((long)HID * HWD));
    long rem = e - (long)b * HID * HWD;
    const float* base = t + (long)b * HID2 * HWD;
    float4 x1 = *reinterpret_cast<const float4*>(&base[rem]);
    float4 x2 = *reinterpret_cast<const float4*>(&base[(long)HID * HWD + rem]);
    float4 o;
    o.x = 0.5f * x1.x * (1.0f + erff(x1.x * 0.70710678118654752f)) * x2.x;
    o.y = 0.5f * x1.y * (1.0f + erff(x1.y * 0.70710678118654752f)) * x2.y;
    o.z = 0.5f * x1.z * (1.0f + erff(x1.z * 0.70710678118654752f)) * x2.z;
    o.w = 0.5f * x1.w * (1.0f + erff(x1.w * 0.70710678118654752f)) * x2.w;
    *reinterpret_cast<float4*>(&g[e]) = o;
}

// ---------------- tf32 tensor-core GEMM ----------------
// C[m,n] (+)= sum_k A(m,k)*B(k,n)
// A addr = m*sma + (k&255)*sakl + (k>>8)*sakh  (per z: + z1*sA1 + z2*sA2)
// B addr = n*snb + (k&255)*sbkl + (k>>8)*sbkh
// BM = MT*64, BN = 64, BK = 16, 128 threads (4 warps, each MT*16 rows x 64 cols)
template<int MT>
__global__ void __launch_bounds__(128) mma_gemm(
    const float* __restrict__ A, const float* __restrict__ B, float* __restrict__ C,
    int M, int N, int K,
    long sma, long sakl, long sakh,
    long snb, long sbkl, long sbkh,
    int ldc, int ksplit, int zdiv,
    long sA1, long sA2, long sB1, long sB2, long sC1, long sC2,
    const float* __restrict__ bias,
    const float* __restrict__ res, long sR1, long sR2,
    const float* __restrict__ ksA, long sKA1,
    const float* __restrict__ ksB, long sKB1,
    int atomic_out, int aCM, int bCN)
{
    const int BM = MT * 64;
    __shared__ float As[MT * 64][20];
    __shared__ float Bs[64][20];

    int z  = blockIdx.z;
    int zb = z / ksplit;
    int ks = z - zb * ksplit;
    int z1 = zb / zdiv, z2 = zb - z1 * zdiv;
    const float* Ap = A + (long)z1 * sA1 + (long)z2 * sA2;
    const float* Bp = B + (long)z1 * sB1 + (long)z2 * sB2;
    float*       Cp = C + (long)z1 * sC1 + (long)z2 * sC2;
    const float* ksAp = ksA ? ksA + (long)z1 * sKA1 : nullptr;
    const float* ksBp = ksB ? ksB + (long)z1 * sKB1 : nullptr;

    int m0 = blockIdx.x * BM;
    int n0 = blockIdx.y * 64;

    int kchunk = ((K + ksplit - 1) / ksplit + 15) & ~15;
    int kbeg = ks * kchunk;
    int kend = min(K, kbeg + kchunk);

    int tid = threadIdx.x;
    int lane = tid & 31, warp = tid >> 5;
    int r = lane >> 2, c = lane & 3;

    float acc[MT * 8][4];
#pragma unroll
    for (int i = 0; i < MT * 8; i++)
#pragma unroll
        for (int j = 0; j < 4; j++) acc[i][j] = 0.f;

    for (int k0 = kbeg; k0 < kend; k0 += 16) {
        int krem = kend - k0;
        const float* At = Ap + (long)(k0 >> 8) * sakh + (long)(k0 & 255) * sakl;
        const float* Bt = Bp + (long)(k0 >> 8) * sbkh + (long)(k0 & 255) * sbkl;

        // ---- load A tile ----
        if (aCM) {
            if (MT == 2) {
                int mm = tid, mg = m0 + mm;
                float vv[16];
#pragma unroll
                for (int i = 0; i < 16; i++) {
                    float v = 0.f;
                    if (mg < M && i < krem) {
                        v = At[(long)mg * sma + (long)i * sakl];
                        if (ksAp) v *= ksAp[k0 + i];
                    }
                    vv[i] = tf32r(v);
                }
#pragma unroll
                for (int i = 0; i < 4; i++)
                    *reinterpret_cast<float4*>(&As[mm][i * 4]) =
                        make_float4(vv[i * 4], vv[i * 4 + 1], vv[i * 4 + 2], vv[i * 4 + 3]);
            } else {
                int mm = tid & 63, kb = (tid >> 6) * 8;
                int mg = m0 + mm;
                float vv[8];
#pragma unroll
                for (int i = 0; i < 8; i++) {
                    int kk = kb + i;
                    float v = 0.f;
                    if (mg < M && kk < krem) {
                        v = At[(long)mg * sma + (long)kk * sakl];
                        if (ksAp) v *= ksAp[k0 + kk];
                    }
                    vv[i] = tf32r(v);
                }
                *reinterpret_cast<float4*>(&As[mm][kb])     = make_float4(vv[0], vv[1], vv[2], vv[3]);
                *reinterpret_cast<float4*>(&As[mm][kb + 4]) = make_float4(vv[4], vv[5], vv[6], vv[7]);
            }
        } else {
#pragma unroll
            for (int i = 0; i < MT * 2; i++) {
                int q = tid + i * 128;
                int mm = q >> 2, k4 = (q & 3) * 4;
                int mg = m0 + mm;
                float vv[4];
#pragma unroll
                for (int j = 0; j < 4; j++) {
                    int kk = k4 + j;
                    float v = 0.f;
                    if (mg < M && kk < krem) {
                        v = At[(long)mg * sma + (long)kk * sakl];
                        if (ksAp) v *= ksAp[k0 + kk];
                    }
                    vv[j] = tf32r(v);
                }
                *reinterpret_cast<float4*>(&As[mm][k4]) = make_float4(vv[0], vv[1], vv[2], vv[3]);
            }
        }

        // ---- load B tile ----
        if (bCN) {
            int nn = tid & 63, kb = (tid >> 6) * 8;
            int ng = n0 + nn;
            float vv[8];
#pragma unroll
            for (int i = 0; i < 8; i++) {
                int kk = kb + i;
                float v = 0.f;
                if (ng < N && kk < krem) {
                    v = Bt[(long)ng * snb + (long)kk * sbkl];
                    if (ksBp) v *= ksBp[k0 + kk];
                }
                vv[i] = tf32r(v);
            }
            *reinterpret_cast<float4*>(&Bs[nn][kb])     = make_float4(vv[0], vv[1], vv[2], vv[3]);
            *reinterpret_cast<float4*>(&Bs[nn][kb + 4]) = make_float4(vv[4], vv[5], vv[6], vv[7]);
        } else {
#pragma unroll
            for (int i = 0; i < 2; i++) {
                int q = tid + i * 128;
                int nn = q >> 2, k4 = (q & 3) * 4;
                int ng = n0 + nn;
                float vv[4];
#pragma unroll
                for (int j = 0; j < 4; j++) {
                    int kk = k4 + j;
                    float v = 0.f;
                    if (ng < N && kk < krem) {
                        v = Bt[(long)ng * snb + (long)kk * sbkl];
                        if (ksBp) v *= ksBp[k0 + kk];
                    }
                    vv[j] = tf32r(v);
                }
                *reinterpret_cast<float4*>(&Bs[nn][k4]) = make_float4(vv[0], vv[1], vv[2], vv[3]);
            }
        }
        __syncthreads();

        // ---- compute ----
#pragma unroll
        for (int ks2 = 0; ks2 < 2; ks2++) {
            int kc = ks2 * 8 + c;
            unsigned a0[MT], a1[MT], a2[MT], a3[MT];
#pragma unroll
            for (int mt = 0; mt < MT; mt++) {
                int mr = warp * (MT * 16) + mt * 16 + r;
                a0[mt] = __float_as_uint(As[mr][kc]);
                a1[mt] = __float_as_uint(As[mr + 8][kc]);
                a2[mt] = __float_as_uint(As[mr][kc + 4]);
                a3[mt] = __float_as_uint(As[mr + 8][kc + 4]);
            }
#pragma unroll
            for (int j = 0; j < 8; j++) {
                unsigned b0 = __float_as_uint(Bs[j * 8 + r][kc]);
                unsigned b1 = __float_as_uint(Bs[j * 8 + r][kc + 4]);
#pragma unroll
                for (int mt = 0; mt < MT; mt++)
                    mma8(acc[mt * 8 + j], a0[mt], a1[mt], a2[mt], a3[mt], b0, b1);
            }
        }
        __syncthreads();
    }

    // ---- epilogue ----
    const float* Rp = res ? res + (long)z1 * sR1 + (long)z2 * sR2 : nullptr;
#pragma unroll
    for (int mt = 0; mt < MT; mt++) {
#pragma unroll
        for (int j = 0; j < 8; j++) {
            int mA = m0 + warp * (MT * 16) + mt * 16 + r;
            int n  = n0 + j * 8 + c * 2;
            float* ci = acc[mt * 8 + j];
#pragma unroll
            for (int half = 0; half < 2; half++) {
                int mrow = mA + half * 8;
                if (mrow >= M || n >= N) continue;
                float bv = bias ? bias[mrow] : 0.f;
                float v0 = ci[half * 2 + 0] + bv;
                float v1 = ci[half * 2 + 1] + bv;
                long off = (long)mrow * ldc + n;
                if (Rp) { v0 += Rp[off]; v1 += Rp[off + 1]; }
                if (atomic_out) {
                    atomicAdd(&Cp[off], v0);
                    atomicAdd(&Cp[off + 1], v1);
                } else {
                    *reinterpret_cast<float2*>(&Cp[off]) = make_float2(v0, v1);
                }
            }
        }
    }
}

// ---------------- host helper ----------------
static void mg(int MT, dim3 grid,
    const float* A, const float* B, float* C,
    int M, int N, int K,
    long sma, long sakl, long sakh,
    long snb, long sbkl, long sbkh,
    int ldc, int ksplit, int zdiv,
    long sA1, long sA2, long sB1, long sB2, long sC1, long sC2,
    const float* bias, const float* res, long sR1, long sR2,
    const float* ksA, long sKA1, const float* ksB, long sKB1,
    int atomic_out, int aCM, int bCN)
{
    if (MT == 2)
        mma_gemm<2><<<grid, 128>>>(A,B,C,M,N,K,sma,sakl,sakh,snb,sbkl,sbkh,ldc,ksplit,zdiv,
            sA1,sA2,sB1,sB2,sC1,sC2,bias,res,sR1,sR2,ksA,sKA1,ksB,sKB1,atomic_out,aCM,bCN);
    else
        mma_gemm<1><<<grid, 128>>>(A,B,C,M,N,K,sma,sakl,sakh,snb,sbkl,sbkh,ldc,ksplit,zdiv,
            sA1,sA2,sB1,sB2,sC1,sC2,bias,res,sR1,sR2,ksA,sKA1,ksB,sKB1,atomic_out,aCM,bCN);
}

extern "C" void kernel_launch(void* const* d_in, const int* in_sizes, int n_in,
                              void* d_out, int out_size)
{
    const float* x        = (const float*)d_in[0];
    const float* w_ln_w   = (const float*)d_in[2];
    const float* w_ln_b   = (const float*)d_in[3];
    const float* w_qkv_w  = (const float*)d_in[4];
    const float* w_qkv_b  = (const float*)d_in[5];
    const float* w_dw_w   = (const float*)d_in[6];
    const float* w_dw_b   = (const float*)d_in[7];
    const float* w_proj_w = (const float*)d_in[8];
    const float* w_proj_b = (const float*)d_in[9];
    const float* w_temp   = (const float*)d_in[10];
    const float* h_ln_w   = (const float*)d_in[11];
    const float* h_ln_b   = (const float*)d_in[12];
    const float* h_qkv_w  = (const float*)d_in[13];
    const float* h_qkv_b  = (const float*)d_in[14];
    const float* h_dw_w   = (const float*)d_in[15];
    const float* h_dw_b   = (const float*)d_in[16];
    const float* h_proj_w = (const float*)d_in[17];
    const float* h_proj_b = (const float*)d_in[18];
    const float* h_temp   = (const float*)d_in[19];
    const float* n2_w     = (const float*)d_in[20];
    const float* n2_b     = (const float*)d_in[21];
    const float* ffn_in_w = (const float*)d_in[22];
    const float* ffn_in_b = (const float*)d_in[23];
    const float* ffn_dw_w = (const float*)d_in[24];
    const float* ffn_dw_b = (const float*)d_in[25];
    const float* ffn_out_w= (const float*)d_in[26];
    const float* ffn_out_b= (const float*)d_in[27];
    float* out = (float*)d_out;

    float *bufA, *bufM, *bufZ, *qkv1, *qkv2, *attn, *invq, *invk, *sq, *sk;
    cudaGetSymbolAddress((void**)&bufA, g_bufA);
    cudaGetSymbolAddress((void**)&bufM, g_bufM);
    cudaGetSymbolAddress((void**)&bufZ, g_bufZ);
    cudaGetSymbolAddress((void**)&qkv1, g_qkv1);
    cudaGetSymbolAddress((void**)&qkv2, g_qkv2);
    cudaGetSymbolAddress((void**)&attn, g_attn);
    cudaGetSymbolAddress((void**)&invq, g_invq);
    cudaGetSymbolAddress((void**)&invk, g_invk);
    cudaGetSymbolAddress((void**)&sq,   g_sq);
    cudaGetSymbolAddress((void**)&sk,   g_sk);

    const long sX = (long)CDIM * HWD;
    const long sQ = (long)3 * CDIM * HWD;
    const long sAT = (long)WW * WW;

    // ================= attention (WxW) =================
    ln_kernel<<<(BATCH * HWD) / 256, 256>>>(x, w_ln_w, w_ln_b, bufA);
    // qkv = W[192,64] @ ln  -> qkv1 [192, HWD]
    mg(2, dim3(2, 1024, BATCH), w_qkv_w, bufA, qkv1, 192, HWD, 64,
       64, 1, 0,   1, HWD, 0,   HWD, 1, 1,
       0,0, sX,0, sQ,0, w_qkv_b, nullptr,0,0, nullptr,0, nullptr,0, 0, 0, 1);
    dwconv4_kernel<<<((long)BATCH*192*HWD/4)/256, 256>>>(qkv1, w_dw_w, w_dw_b, qkv2, 192);
    rowinv_kernel<<<dim3(CHROWS/8, BATCH), 256>>>(qkv2,                sQ, invq);
    rowinv_kernel<<<dim3(CHROWS/8, BATCH), 256>>>(qkv2 + 64*(long)HWD, sQ, invk);
    cudaMemsetAsync(attn, 0, (size_t)BATCH * WW * WW * sizeof(float));
    // gram: attn[w,u] = sum_k qhat^T khat ; A addr = k*WW + m
    mg(2, dim3(2, 4, BATCH*16), qkv2, qkv2 + 64*(long)HWD, attn, 256, 256, CHROWS,
       1, WW, (long)WW*256,   1, WW, (long)WW*256,   WW, 16, 1,
       sQ,0, sQ,0, sAT,0, nullptr, nullptr,0,0, invq, CHROWS, invk, CHROWS, 1, 1, 1);
    softmax_kernel<<<dim3(WW, BATCH), 256>>>(attn, w_temp, nullptr, nullptr);
    // AV: [16384,256] @ attn[256,256]
    mg(2, dim3(128, 4, BATCH), qkv2 + 128*(long)HWD, attn, bufA, CHROWS, 256, 256,
       WW, 1, 0,   1, WW, 0,   WW, 1, 1,
       sQ,0, sAT,0, sX,0, nullptr, nullptr,0,0, nullptr,0, nullptr,0, 0, 0, 1);
    // proj + residual x -> bufM
    mg(1, dim3(1, 1024, BATCH), w_proj_w, bufA, bufM, 64, HWD, 64,
       64, 1, 0,   1, HWD, 0,   HWD, 1, 1,
       0,0, sX,0, sX,0, w_proj_b, x, sX,0, nullptr,0, nullptr,0, 0, 0, 1);

    // ================= attention (HxH) =================
    ln_kernel<<<(BATCH * HWD) / 256, 256>>>(bufM, h_ln_w, h_ln_b, bufA);
    mg(2, dim3(2, 1024, BATCH), h_qkv_w, bufA, qkv1, 192, HWD, 64,
       64, 1, 0,   1, HWD, 0,   HWD, 1, 1,
       0,0, sX,0, sQ,0, h_qkv_b, nullptr,0,0, nullptr,0, nullptr,0, 0, 0, 1);
    dwconv4_kernel<<<((long)BATCH*192*HWD/4)/256, 256>>>(qkv1, h_dw_w, h_dw_b, qkv2, 192);
    hnorm_kernel<<<dim3(HH, BATCH), 256>>>(qkv2,                sq);
    hnorm_kernel<<<dim3(HH, BATCH), 256>>>(qkv2 + 64*(long)HWD, sk);
    cudaMemsetAsync(attn, 0, (size_t)BATCH * WW * WW * sizeof(float));
    // gram: attn[h,g] = sum_{c,w} q[c,h,w] k[c,g,w]; addr = m*WW + (k&255) + (k>>8)*HWD
    mg(2, dim3(2, 4, BATCH*16), qkv2, qkv2 + 64*(long)HWD, attn, 256, 256, CHROWS,
       WW, 1, (long)HWD,   WW, 1, (long)HWD,   WW, 16, 1,
       sQ,0, sQ,0, sAT,0, nullptr, nullptr,0,0, nullptr,0, nullptr,0, 1, 0, 0);
    softmax_kernel<<<dim3(WW, BATCH), 256>>>(attn, h_temp, sq, sk);
    // AV: per (b,c): attn[256,256] @ v[c][256,256]
    mg(2, dim3(2, 4, BATCH*64), attn, qkv2 + 128*(long)HWD, bufA, 256, 256, 256,
       WW, 1, 0,   1, WW, 0,   WW, 1, 64,
       sAT,0, sQ,(long)HWD, sX,(long)HWD, nullptr, nullptr,0,0, nullptr,0, nullptr,0, 0, 0, 1);
    // proj + residual m -> bufZ
    mg(1, dim3(1, 1024, BATCH), h_proj_w, bufA, bufZ, 64, HWD, 64,
       64, 1, 0,   1, HWD, 0,   HWD, 1, 1,
       0,0, sX,0, sX,0, h_proj_b, bufM, sX,0, nullptr,0, nullptr,0, 0, 0, 1);

    // ================= FFN =================
    ln_kernel<<<(BATCH * HWD) / 256, 256>>>(bufZ, n2_w, n2_b, bufA);
    mg(2, dim3(3, 1024, BATCH), ffn_in_w, bufA, qkv1, HID2, HWD, 64,
       64, 1, 0,   1, HWD, 0,   HWD, 1, 1,
       0,0, sX,0, (long)HID2*HWD,0, ffn_in_b, nullptr,0,0, nullptr,0, nullptr,0, 0, 0, 1);
    dwconv4_kernel<<<((long)BATCH*HID2*HWD/4)/256, 256>>>(qkv1, ffn_dw_w, ffn_dw_b, qkv2, HID2);
    gate4_kernel<<<((long)BATCH*HID*HWD/4 + 255)/256, 256>>>(qkv2, qkv1);
    mg(1, dim3(1, 1024, BATCH), ffn_out_w, qkv1, out, 64, HWD, 170,
       170, 1, 0,   1, HWD, 0,   HWD, 1, 1,
       0,0, (long)HID*HWD,0, sX,0, ffn_out_b, bufZ, sX,0, nullptr,0, nullptr,0, 0, 0, 1);
}

// round 3
// speedup vs baseline: 1.6201x; 1.0838x over previous
#include <cuda_runtime.h>
#include <math.h>

#define BATCH 4
#define CDIM  64
#define HH    256
#define WW    256
#define HWD   65536          // H*W
#define CHROWS 16384         // C*H
#define HID   170
#define HID2  340

// ---------------- scratch (device globals; no allocations allowed) ----------------
__device__ float g_bufA[(size_t)BATCH * CDIM * HWD];
__device__ float g_bufM[(size_t)BATCH * CDIM * HWD];
__device__ float g_bufZ[(size_t)BATCH * CDIM * HWD];
__device__ float g_qkv1[(size_t)BATCH * HID2 * HWD];
__device__ float g_qkv2[(size_t)BATCH * HID2 * HWD];
__device__ float g_attn[(size_t)BATCH * WW * WW];
__device__ float g_inv2[(size_t)BATCH * 2 * CHROWS];   // invq | invk, per batch
__device__ float g_sq[BATCH * HH];
__device__ float g_sk[BATCH * HH];

// ---------------- helpers ----------------
__device__ __forceinline__ float tf32r(float v) {
    unsigned u;
    asm("cvt.rna.tf32.f32 %0, %1;" : "=r"(u) : "f"(v));
    return __uint_as_float(u);
}
__device__ __forceinline__ void mma8(float* d, unsigned a0, unsigned a1, unsigned a2, unsigned a3,
                                     unsigned b0, unsigned b1) {
    asm volatile(
        "mma.sync.aligned.m16n8k8.row.col.f32.tf32.tf32.f32 "
        "{%0,%1,%2,%3},{%4,%5,%6,%7},{%8,%9},{%0,%1,%2,%3};\n"
        : "+f"(d[0]), "+f"(d[1]), "+f"(d[2]), "+f"(d[3])
        : "r"(a0), "r"(a1), "r"(a2), "r"(a3), "r"(b0), "r"(b1));
}

// ---------------- LayerNorm over channel dim (per pixel) ----------------
__global__ void ln_kernel(const float* __restrict__ x, const float* __restrict__ w,
                          const float* __restrict__ b, float* __restrict__ y)
{
    long p = (long)blockIdx.x * blockDim.x + threadIdx.x;
    if (p >= (long)BATCH * HWD) return;
    int bb  = (int)(p >> 16);
    int pix = (int)(p & (HWD - 1));
    const float* xp = x + (long)bb * CDIM * HWD + pix;
    float s = 0.f, s2 = 0.f;
#pragma unroll
    for (int c = 0; c < CDIM; c++) {
        float v = xp[(long)c * HWD];
        s += v; s2 += v * v;
    }
    float mu  = s * (1.0f / CDIM);
    float var = s2 * (1.0f / CDIM) - mu * mu;
    float inv = rsqrtf(var + 1e-5f);
    float* yp = y + (long)bb * CDIM * HWD + pix;
#pragma unroll
    for (int c = 0; c < CDIM; c++) {
        float v = xp[(long)c * HWD];
        yp[(long)c * HWD] = (v - mu) * inv * w[c] + b[c];
    }
}

// ---------------- row-oriented depthwise 3x3 + optional per-row inverse L2 norm --------
// block = 256 threads = 4 consecutive h-rows of one (b, c); each row: 64 thr x 4 px.
// norm_out layout per batch: [2*CHROWS], index c*HH + h for c < normCh.
__global__ void dwconv_rows_kernel(const float* __restrict__ x, const float* __restrict__ wt,
                                   const float* __restrict__ bias, float* __restrict__ y,
                                   int OC, float* __restrict__ norm_out, int normCh)
{
    long bidx = blockIdx.x;
    int hb = (int)(bidx & 63) * 4;         // HH/4 = 64
    long bc = bidx >> 6;                    // b*OC + c
    int c = (int)(bc % OC);
    int b = (int)(bc / OC);
    int rowid = threadIdx.x >> 6;
    int t = threadIdx.x & 63;
    int h = hb + rowid;
    int w4 = t * 4;
    const float* xp = x + (bc << 16);
    float b0 = bias[c];
    float acc0 = b0, acc1 = b0, acc2 = b0, acc3 = b0;
#pragma unroll
    for (int kh = -1; kh <= 1; kh++) {
        int hh = h + kh;
        if (hh < 0 || hh >= HH) continue;
        const float* row = xp + hh * WW;
        float vm1 = (w4 > 0)      ? row[w4 - 1] : 0.f;
        float4 v  = *reinterpret_cast<const float4*>(&row[w4]);
        float vp4 = (w4 + 4 < WW) ? row[w4 + 4] : 0.f;
        float vals[6] = {vm1, v.x, v.y, v.z, v.w, vp4};
        const float* wr = wt + c * 9 + (kh + 1) * 3;
#pragma unroll
        for (int kw = 0; kw < 3; kw++) {
            float g = wr[kw];
            acc0 = fmaf(g, vals[kw + 0], acc0);
            acc1 = fmaf(g, vals[kw + 1], acc1);
            acc2 = fmaf(g, vals[kw + 2], acc2);
            acc3 = fmaf(g, vals[kw + 3], acc3);
        }
    }
    *reinterpret_cast<float4*>(&y[(bc << 16) + h * WW + w4]) = make_float4(acc0, acc1, acc2, acc3);

    if (norm_out) {
        float s = acc0 * acc0 + acc1 * acc1 + acc2 * acc2 + acc3 * acc3;
#pragma unroll
        for (int o = 16; o > 0; o >>= 1) s += __shfl_down_sync(0xffffffffu, s, o);
        __shared__ float part[8];
        int warp = threadIdx.x >> 5, lane = threadIdx.x & 31;
        if (lane == 0) part[warp] = s;
        __syncthreads();
        if (t == 0 && c < normCh) {
            float tot = part[rowid * 2] + part[rowid * 2 + 1];
            norm_out[(long)b * 2 * CHROWS + c * HH + h] = 1.f / fmaxf(sqrtf(tot), 1e-12f);
        }
    }
}

// ---------------- fused FFN depthwise 3x3 + GELU gate ----------------
// out[b, c, p] = gelu(dw(x1)[b,c,p]) * dw(x2)[b,c+HID,p]
__global__ void dwconv_gate_kernel(const float* __restrict__ x, const float* __restrict__ wt,
                                   const float* __restrict__ bias, float* __restrict__ g)
{
    long idx = (long)blockIdx.x * blockDim.x + threadIdx.x;
    long total = (long)BATCH * HID * (HWD / 4);
    if (idx >= total) return;
    int w4 = (int)(idx & 63) * 4;
    int h  = (int)((idx >> 6) & 255);
    long bc = idx >> 14;
    int c = (int)(bc % HID);
    int b = (int)(bc / HID);
    const float* xp1 = x + ((long)b * HID2 + c) * HWD;
    const float* xp2 = xp1 + (long)HID * HWD;
    float bb1 = bias[c], bb2 = bias[c + HID];
    float a0 = bb1, a1 = bb1, a2 = bb1, a3 = bb1;
    float c0 = bb2, c1 = bb2, c2 = bb2, c3 = bb2;
    const float* w1 = wt + c * 9;
    const float* w2 = wt + (c + HID) * 9;
#pragma unroll
    for (int kh = -1; kh <= 1; kh++) {
        int hh = h + kh;
        if (hh < 0 || hh >= HH) continue;
        {
            const float* row = xp1 + hh * WW;
            float vm1 = (w4 > 0)      ? row[w4 - 1] : 0.f;
            float4 v  = *reinterpret_cast<const float4*>(&row[w4]);
            float vp4 = (w4 + 4 < WW) ? row[w4 + 4] : 0.f;
            float vals[6] = {vm1, v.x, v.y, v.z, v.w, vp4};
            const float* wr = w1 + (kh + 1) * 3;
#pragma unroll
            for (int kw = 0; kw < 3; kw++) {
                float gg = wr[kw];
                a0 = fmaf(gg, vals[kw + 0], a0);
                a1 = fmaf(gg, vals[kw + 1], a1);
                a2 = fmaf(gg, vals[kw + 2], a2);
                a3 = fmaf(gg, vals[kw + 3], a3);
            }
        }
        {
            const float* row = xp2 + hh * WW;
            float vm1 = (w4 > 0)      ? row[w4 - 1] : 0.f;
            float4 v  = *reinterpret_cast<const float4*>(&row[w4]);
            float vp4 = (w4 + 4 < WW) ? row[w4 + 4] : 0.f;
            float vals[6] = {vm1, v.x, v.y, v.z, v.w, vp4};
            const float* wr = w2 + (kh + 1) * 3;
#pragma unroll
            for (int kw = 0; kw < 3; kw++) {
                float gg = wr[kw];
                c0 = fmaf(gg, vals[kw + 0], c0);
                c1 = fmaf(gg, vals[kw + 1], c1);
                c2 = fmaf(gg, vals[kw + 2], c2);
                c3 = fmaf(gg, vals[kw + 3], c3);
            }
        }
    }
    const float k = 0.70710678118654752f;
    float4 o;
    o.x = 0.5f * a0 * (1.0f + erff(a0 * k)) * c0;
    o.y = 0.5f * a1 * (1.0f + erff(a1 * k)) * c1;
    o.z = 0.5f * a2 * (1.0f + erff(a2 * k)) * c2;
    o.w = 0.5f * a3 * (1.0f + erff(a3 * k)) * c3;
    *reinterpret_cast<float4*>(&g[((long)b * HID + c) * HWD + h * WW + w4]) = o;
}

// ---------------- hxh inverse norm: per (b,h) over (c,w) ----------------
__global__ void hnorm_kernel(const float* __restrict__ src, float* __restrict__ out)
{
    int b = blockIdx.y, h = blockIdx.x;
    int t = threadIdx.x;
    const float* p = src + (long)b * (3 * CDIM) * HWD + (long)h * WW + t;
    float s = 0.f;
#pragma unroll
    for (int c = 0; c < CDIM; c++) { float v = p[(long)c * HWD]; s += v * v; }
    __shared__ float red[256];
    red[t] = s; __syncthreads();
    for (int o = 128; o > 0; o >>= 1) { if (t < o) red[t] += red[t + o]; __syncthreads(); }
    if (t == 0) out[b * HH + h] = 1.f / fmaxf(sqrtf(red[0]), 1e-12f);
}

// ---------------- softmax over last dim of [B, 256, 256] ----------------
__global__ void softmax_kernel(float* __restrict__ attn, const float* __restrict__ temp,
                               const float* __restrict__ sq, const float* __restrict__ sk)
{
    int b = blockIdx.y;
    int r = blockIdx.x;
    float* row = attn + ((long)b * WW + r) * WW;
    int t = threadIdx.x;
    float v = row[t] * temp[0];
    if (sq) v *= sq[b * WW + r] * sk[b * WW + t];
    __shared__ float red[256];
    red[t] = v; __syncthreads();
    for (int o = 128; o > 0; o >>= 1) { if (t < o) red[t] = fmaxf(red[t], red[t + o]); __syncthreads(); }
    float mx = red[0]; __syncthreads();
    float e = __expf(v - mx);
    red[t] = e; __syncthreads();
    for (int o = 128; o > 0; o >>= 1) { if (t < o) red[t] += red[t + o]; __syncthreads(); }
    row[t] = e * (1.f / red[0]);
}

// ---------------- tf32 tensor-core GEMM, register-staged double buffering ----------------
// C[m,n] (+)= sum_k A(m,k)*B(k,n)
// A addr = m*sma + (k&255)*sakl + (k>>8)*sakh  (per z: + z1*sA1 + z2*sA2)
// B addr = n*snb + (k&255)*sbkl + (k>>8)*sbkh
// BM = MT*64, BN = 64, BK = 16, 128 threads (4 warps, each MT*16 rows x 64 cols)
template<int MT>
__global__ void __launch_bounds__(128, 3) mma_gemm(
    const float* __restrict__ A, const float* __restrict__ B, float* __restrict__ C,
    int M, int N, int K,
    long sma, long sakl, long sakh,
    long snb, long sbkl, long sbkh,
    int ldc, int ksplit, int zdiv,
    long sA1, long sA2, long sB1, long sB2, long sC1, long sC2,
    const float* __restrict__ bias,
    const float* __restrict__ res, long sR1, long sR2,
    const float* __restrict__ ksA, long sKA1,
    const float* __restrict__ ksB, long sKB1,
    int atomic_out, int aCM, int bCN)
{
    const int BM = MT * 64;
    __shared__ float As[MT * 64][20];
    __shared__ float Bs[64][20];

    int z  = blockIdx.z;
    int zb = z / ksplit;
    int ks = z - zb * ksplit;
    int z1 = zb / zdiv, z2 = zb - z1 * zdiv;
    const float* Ap = A + (long)z1 * sA1 + (long)z2 * sA2;
    const float* Bp = B + (long)z1 * sB1 + (long)z2 * sB2;
    float*       Cp = C + (long)z1 * sC1 + (long)z2 * sC2;
    const float* ksAp = ksA ? ksA + (long)z1 * sKA1 : nullptr;
    const float* ksBp = ksB ? ksB + (long)z1 * sKB1 : nullptr;

    int m0 = blockIdx.x * BM;
    int n0 = blockIdx.y * 64;

    int kchunk = ((K + ksplit - 1) / ksplit + 15) & ~15;
    int kbeg = ks * kchunk;
    int kend = min(K, kbeg + kchunk);

    int tid = threadIdx.x;
    int lane = tid & 31, warp = tid >> 5;
    int r = lane >> 2, c = lane & 3;

    float ra[16];   // staged A tile fragment (per-thread)
    float rb[8];    // staged B tile fragment

    auto loadA = [&](int k0) {
        int krem = kend - k0;
        const float* At = Ap + (long)(k0 >> 8) * sakh + (long)(k0 & 255) * sakl;
        if (aCM) {
            if (MT == 2) {
                int mg = m0 + tid;
#pragma unroll
                for (int i = 0; i < 16; i++) {
                    float v = 0.f;
                    if (mg < M && i < krem) {
                        v = At[(long)mg * sma + (long)i * sakl];
                        if (ksAp) v *= ksAp[k0 + i];
                    }
                    ra[i] = v;
                }
            } else {
                int mg = m0 + (tid & 63), kb = (tid >> 6) * 8;
#pragma unroll
                for (int i = 0; i < 8; i++) {
                    int kk = kb + i;
                    float v = 0.f;
                    if (mg < M && kk < krem) {
                        v = At[(long)mg * sma + (long)kk * sakl];
                        if (ksAp) v *= ksAp[k0 + kk];
                    }
                    ra[i] = v;
                }
            }
        } else {
#pragma unroll
            for (int i = 0; i < MT * 2; i++) {
                int q = tid + i * 128;
                int mg = m0 + (q >> 2), k4 = (q & 3) * 4;
#pragma unroll
                for (int j = 0; j < 4; j++) {
                    int kk = k4 + j;
                    float v = 0.f;
                    if (mg < M && kk < krem) {
                        v = At[(long)mg * sma + (long)kk * sakl];
                        if (ksAp) v *= ksAp[k0 + kk];
                    }
                    ra[i * 4 + j] = v;
                }
            }
        }
    };

    auto loadB = [&](int k0) {
        int krem = kend - k0;
        const float* Bt = Bp + (long)(k0 >> 8) * sbkh + (long)(k0 & 255) * sbkl;
        if (bCN) {
            int ng = n0 + (tid & 63), kb = (tid >> 6) * 8;
#pragma unroll
            for (int i = 0; i < 8; i++) {
                int kk = kb + i;
                float v = 0.f;
                if (ng < N && kk < krem) {
                    v = Bt[(long)ng * snb + (long)kk * sbkl];
                    if (ksBp) v *= ksBp[k0 + kk];
                }
                rb[i] = v;
            }
        } else {
#pragma unroll
            for (int i = 0; i < 2; i++) {
                int q = tid + i * 128;
                int ng = n0 + (q >> 2), k4 = (q & 3) * 4;
#pragma unroll
                for (int j = 0; j < 4; j++) {
                    int kk = k4 + j;
                    float v = 0.f;
                    if (ng < N && kk < krem) {
                        v = Bt[(long)ng * snb + (long)kk * sbkl];
                        if (ksBp) v *= ksBp[k0 + kk];
                    }
                    rb[i * 4 + j] = v;
                }
            }
        }
    };

    auto stsAB = [&]() {
        if (aCM) {
            if (MT == 2) {
#pragma unroll
                for (int i = 0; i < 4; i++)
                    *reinterpret_cast<float4*>(&As[tid][i * 4]) =
                        make_float4(tf32r(ra[i*4]), tf32r(ra[i*4+1]), tf32r(ra[i*4+2]), tf32r(ra[i*4+3]));
            } else {
                int mm = tid & 63, kb = (tid >> 6) * 8;
                *reinterpret_cast<float4*>(&As[mm][kb])     =
                    make_float4(tf32r(ra[0]), tf32r(ra[1]), tf32r(ra[2]), tf32r(ra[3]));
                *reinterpret_cast<float4*>(&As[mm][kb + 4]) =
                    make_float4(tf32r(ra[4]), tf32r(ra[5]), tf32r(ra[6]), tf32r(ra[7]));
            }
        } else {
#pragma unroll
            for (int i = 0; i < MT * 2; i++) {
                int q = tid + i * 128;
                int mm = q >> 2, k4 = (q & 3) * 4;
                *reinterpret_cast<float4*>(&As[mm][k4]) =
                    make_float4(tf32r(ra[i*4]), tf32r(ra[i*4+1]), tf32r(ra[i*4+2]), tf32r(ra[i*4+3]));
            }
        }
        if (bCN) {
            int nn = tid & 63, kb = (tid >> 6) * 8;
            *reinterpret_cast<float4*>(&Bs[nn][kb])     =
                make_float4(tf32r(rb[0]), tf32r(rb[1]), tf32r(rb[2]), tf32r(rb[3]));
            *reinterpret_cast<float4*>(&Bs[nn][kb + 4]) =
                make_float4(tf32r(rb[4]), tf32r(rb[5]), tf32r(rb[6]), tf32r(rb[7]));
        } else {
#pragma unroll
            for (int i = 0; i < 2; i++) {
                int q = tid + i * 128;
                int nn = q >> 2, k4 = (q & 3) * 4;
                *reinterpret_cast<float4*>(&Bs[nn][k4]) =
                    make_float4(tf32r(rb[i*4]), tf32r(rb[i*4+1]), tf32r(rb[i*4+2]), tf32r(rb[i*4+3]));
            }
        }
    };

    float acc[MT * 8][4];
#pragma unroll
    for (int i = 0; i < MT * 8; i++)
#pragma unroll
        for (int j = 0; j < 4; j++) acc[i][j] = 0.f;

    loadA(kbeg);
    loadB(kbeg);

    for (int k0 = kbeg; k0 < kend; k0 += 16) {
        stsAB();
        __syncthreads();
        int kn = k0 + 16;
        if (kn < kend) { loadA(kn); loadB(kn); }

#pragma unroll
        for (int ks2 = 0; ks2 < 2; ks2++) {
            int kc = ks2 * 8 + c;
            unsigned a0[MT], a1[MT], a2[MT], a3[MT];
#pragma unroll
            for (int mt = 0; mt < MT; mt++) {
                int mr = warp * (MT * 16) + mt * 16 + r;
                a0[mt] = __float_as_uint(As[mr][kc]);
                a1[mt] = __float_as_uint(As[mr + 8][kc]);
                a2[mt] = __float_as_uint(As[mr][kc + 4]);
                a3[mt] = __float_as_uint(As[mr + 8][kc + 4]);
            }
#pragma unroll
            for (int j = 0; j < 8; j++) {
                unsigned b0 = __float_as_uint(Bs[j * 8 + r][kc]);
                unsigned b1 = __float_as_uint(Bs[j * 8 + r][kc + 4]);
#pragma unroll
                for (int mt = 0; mt < MT; mt++)
                    mma8(acc[mt * 8 + j], a0[mt], a1[mt], a2[mt], a3[mt], b0, b1);
            }
        }
        __syncthreads();
    }

    // ---- epilogue ----
    const float* Rp = res ? res + (long)z1 * sR1 + (long)z2 * sR2 : nullptr;
#pragma unroll
    for (int mt = 0; mt < MT; mt++) {
#pragma unroll
        for (int j = 0; j < 8; j++) {
            int mA = m0 + warp * (MT * 16) + mt * 16 + r;
            int n  = n0 + j * 8 + c * 2;
            float* ci = acc[mt * 8 + j];
#pragma unroll
            for (int half = 0; half < 2; half++) {
                int mrow = mA + half * 8;
                if (mrow >= M || n >= N) continue;
                float bv = bias ? bias[mrow] : 0.f;
                float v0 = ci[half * 2 + 0] + bv;
                float v1 = ci[half * 2 + 1] + bv;
                long off = (long)mrow * ldc + n;
                if (Rp) { v0 += Rp[off]; v1 += Rp[off + 1]; }
                if (atomic_out) {
                    atomicAdd(&Cp[off], v0);
                    atomicAdd(&Cp[off + 1], v1);
                } else {
                    *reinterpret_cast<float2*>(&Cp[off]) = make_float2(v0, v1);
                }
            }
        }
    }
}

// ---------------- host helper ----------------
static void mg(int MT, dim3 grid,
    const float* A, const float* B, float* C,
    int M, int N, int K,
    long sma, long sakl, long sakh,
    long snb, long sbkl, long sbkh,
    int ldc, int ksplit, int zdiv,
    long sA1, long sA2, long sB1, long sB2, long sC1, long sC2,
    const float* bias, const float* res, long sR1, long sR2,
    const float* ksA, long sKA1, const float* ksB, long sKB1,
    int atomic_out, int aCM, int bCN)
{
    if (MT == 2)
        mma_gemm<2><<<grid, 128>>>(A,B,C,M,N,K,sma,sakl,sakh,snb,sbkl,sbkh,ldc,ksplit,zdiv,
            sA1,sA2,sB1,sB2,sC1,sC2,bias,res,sR1,sR2,ksA,sKA1,ksB,sKB1,atomic_out,aCM,bCN);
    else
        mma_gemm<1><<<grid, 128>>>(A,B,C,M,N,K,sma,sakl,sakh,snb,sbkl,sbkh,ldc,ksplit,zdiv,
            sA1,sA2,sB1,sB2,sC1,sC2,bias,res,sR1,sR2,ksA,sKA1,ksB,sKB1,atomic_out,aCM,bCN);
}

extern "C" void kernel_launch(void* const* d_in, const int* in_sizes, int n_in,
                              void* d_out, int out_size)
{
    const float* x        = (const float*)d_in[0];
    const float* w_ln_w   = (const float*)d_in[2];
    const float* w_ln_b   = (const float*)d_in[3];
    const float* w_qkv_w  = (const float*)d_in[4];
    const float* w_qkv_b  = (const float*)d_in[5];
    const float* w_dw_w   = (const float*)d_in[6];
    const float* w_dw_b   = (const float*)d_in[7];
    const float* w_proj_w = (const float*)d_in[8];
    const float* w_proj_b = (const float*)d_in[9];
    const float* w_temp   = (const float*)d_in[10];
    const float* h_ln_w   = (const float*)d_in[11];
    const float* h_ln_b   = (const float*)d_in[12];
    const float* h_qkv_w  = (const float*)d_in[13];
    const float* h_qkv_b  = (const float*)d_in[14];
    const float* h_dw_w   = (const float*)d_in[15];
    const float* h_dw_b   = (const float*)d_in[16];
    const float* h_proj_w = (const float*)d_in[17];
    const float* h_proj_b = (const float*)d_in[18];
    const float* h_temp   = (const float*)d_in[19];
    const float* n2_w     = (const float*)d_in[20];
    const float* n2_b     = (const float*)d_in[21];
    const float* ffn_in_w = (const float*)d_in[22];
    const float* ffn_in_b = (const float*)d_in[23];
    const float* ffn_dw_w = (const float*)d_in[24];
    const float* ffn_dw_b = (const float*)d_in[25];
    const float* ffn_out_w= (const float*)d_in[26];
    const float* ffn_out_b= (const float*)d_in[27];
    float* out = (float*)d_out;

    float *bufA, *bufM, *bufZ, *qkv1, *qkv2, *attn, *inv2, *sq, *sk;
    cudaGetSymbolAddress((void**)&bufA, g_bufA);
    cudaGetSymbolAddress((void**)&bufM, g_bufM);
    cudaGetSymbolAddress((void**)&bufZ, g_bufZ);
    cudaGetSymbolAddress((void**)&qkv1, g_qkv1);
    cudaGetSymbolAddress((void**)&qkv2, g_qkv2);
    cudaGetSymbolAddress((void**)&attn, g_attn);
    cudaGetSymbolAddress((void**)&inv2, g_inv2);
    cudaGetSymbolAddress((void**)&sq,   g_sq);
    cudaGetSymbolAddress((void**)&sk,   g_sk);

    const long sX = (long)CDIM * HWD;
    const long sQ = (long)3 * CDIM * HWD;
    const long sAT = (long)WW * WW;
    const long sI2 = (long)2 * CHROWS;

    // ================= attention (WxW) =================
    ln_kernel<<<(BATCH * HWD) / 256, 256>>>(x, w_ln_w, w_ln_b, bufA);
    mg(2, dim3(2, 1024, BATCH), w_qkv_w, bufA, qkv1, 192, HWD, 64,
       64, 1, 0,   1, HWD, 0,   HWD, 1, 1,
       0,0, sX,0, sQ,0, w_qkv_b, nullptr,0,0, nullptr,0, nullptr,0, 0, 0, 1);
    dwconv_rows_kernel<<<BATCH*192*64, 256>>>(qkv1, w_dw_w, w_dw_b, qkv2, 192, inv2, 128);
    cudaMemsetAsync(attn, 0, (size_t)BATCH * WW * WW * sizeof(float));
    // gram: attn[w,u] = sum_k qhat^T khat
    mg(2, dim3(2, 4, BATCH*16), qkv2, qkv2 + 64*(long)HWD, attn, 256, 256, CHROWS,
       1, WW, (long)WW*256,   1, WW, (long)WW*256,   WW, 16, 1,
       sQ,0, sQ,0, sAT,0, nullptr, nullptr,0,0, inv2, sI2, inv2 + CHROWS, sI2, 1, 1, 1);
    softmax_kernel<<<dim3(WW, BATCH), 256>>>(attn, w_temp, nullptr, nullptr);
    // AV
    mg(2, dim3(128, 4, BATCH), qkv2 + 128*(long)HWD, attn, bufA, CHROWS, 256, 256,
       WW, 1, 0,   1, WW, 0,   WW, 1, 1,
       sQ,0, sAT,0, sX,0, nullptr, nullptr,0,0, nullptr,0, nullptr,0, 0, 0, 1);
    // proj + residual x -> bufM
    mg(1, dim3(1, 1024, BATCH), w_proj_w, bufA, bufM, 64, HWD, 64,
       64, 1, 0,   1, HWD, 0,   HWD, 1, 1,
       0,0, sX,0, sX,0, w_proj_b, x, sX,0, nullptr,0, nullptr,0, 0, 0, 1);

    // ================= attention (HxH) =================
    ln_kernel<<<(BATCH * HWD) / 256, 256>>>(bufM, h_ln_w, h_ln_b, bufA);
    mg(2, dim3(2, 1024, BATCH), h_qkv_w, bufA, qkv1, 192, HWD, 64,
       64, 1, 0,   1, HWD, 0,   HWD, 1, 1,
       0,0, sX,0, sQ,0, h_qkv_b, nullptr,0,0, nullptr,0, nullptr,0, 0, 0, 1);
    dwconv_rows_kernel<<<BATCH*192*64, 256>>>(qkv1, h_dw_w, h_dw_b, qkv2, 192, nullptr, 0);
    hnorm_kernel<<<dim3(HH, BATCH), 256>>>(qkv2,                sq);
    hnorm_kernel<<<dim3(HH, BATCH), 256>>>(qkv2 + 64*(long)HWD, sk);
    cudaMemsetAsync(attn, 0, (size_t)BATCH * WW * WW * sizeof(float));
    // gram: attn[h,g] = sum_{c,w} q[c,h,w] k[c,g,w]
    mg(2, dim3(2, 4, BATCH*16), qkv2, qkv2 + 64*(long)HWD, attn, 256, 256, CHROWS,
       WW, 1, (long)HWD,   WW, 1, (long)HWD,   WW, 16, 1,
       sQ,0, sQ,0, sAT,0, nullptr, nullptr,0,0, nullptr,0, nullptr,0, 1, 0, 0);
    softmax_kernel<<<dim3(WW, BATCH), 256>>>(attn, h_temp, sq, sk);
    // AV: per (b,c): attn[256,256] @ v[c][256,256]
    mg(2, dim3(2, 4, BATCH*64), attn, qkv2 + 128*(long)HWD, bufA, 256, 256, 256,
       WW, 1, 0,   1, WW, 0,   WW, 1, 64,
       sAT,0, sQ,(long)HWD, sX,(long)HWD, nullptr, nullptr,0,0, nullptr,0, nullptr,0, 0, 0, 1);
    // proj + residual m -> bufZ
    mg(1, dim3(1, 1024, BATCH), h_proj_w, bufA, bufZ, 64, HWD, 64,
       64, 1, 0,   1, HWD, 0,   HWD, 1, 1,
       0,0, sX,0, sX,0, h_proj_b, bufM, sX,0, nullptr,0, nullptr,0, 0, 0, 1);

    // ================= FFN =================
    ln_kernel<<<(BATCH * HWD) / 256, 256>>>(bufZ, n2_w, n2_b, bufA);
    mg(2, dim3(3, 1024, BATCH), ffn_in_w, bufA, qkv1, HID2, HWD, 64,
       64, 1, 0,   1, HWD, 0,   HWD, 1, 1,
       0,0, sX,0, (long)HID2*HWD,0, ffn_in_b, nullptr,0,0, nullptr,0, nullptr,0, 0, 0, 1);
    dwconv_gate_kernel<<<((long)BATCH*HID*HWD/4 + 255)/256, 256>>>(qkv1, ffn_dw_w, ffn_dw_b, qkv2);
    mg(1, dim3(1, 1024, BATCH), ffn_out_w, qkv2, out, 64, HWD, 170,
       170, 1, 0,   1, HWD, 0,   HWD, 1, 1,
       0,0, (long)HID*HWD,0, sX,0, ffn_out_b, bufZ, sX,0, nullptr,0, nullptr,0, 0, 0, 1);
}

// round 4
// speedup vs baseline: 2.3381x; 1.4432x over previous
#include <cuda_runtime.h>
#include <math.h>

#define BATCH 4
#define CDIM  64
#define HH    256
#define WW    256
#define HWD   65536          // H*W
#define CHROWS 16384         // C*H
#define HID   170
#define HID2  340

// ---------------- scratch (device globals; no allocations allowed) ----------------
__device__ float g_bufA[(size_t)BATCH * CDIM * HWD];
__device__ float g_bufM[(size_t)BATCH * CDIM * HWD];
__device__ float g_bufZ[(size_t)BATCH * CDIM * HWD];
__device__ float g_qkv1[(size_t)BATCH * HID2 * HWD];
__device__ float g_qkv2[(size_t)BATCH * HID2 * HWD];
__device__ float g_attn[(size_t)BATCH * WW * WW];
__device__ float g_sq[BATCH * HH];
__device__ float g_sk[BATCH * HH];

// ---------------- helpers ----------------
__device__ __forceinline__ float tf32r(float v) {
    unsigned u;
    asm("cvt.rna.tf32.f32 %0, %1;" : "=r"(u) : "f"(v));
    return __uint_as_float(u);
}
__device__ __forceinline__ void mma8(float* d, unsigned a0, unsigned a1, unsigned a2, unsigned a3,
                                     unsigned b0, unsigned b1) {
    asm volatile(
        "mma.sync.aligned.m16n8k8.row.col.f32.tf32.tf32.f32 "
        "{%0,%1,%2,%3},{%4,%5,%6,%7},{%8,%9},{%0,%1,%2,%3};\n"
        : "+f"(d[0]), "+f"(d[1]), "+f"(d[2]), "+f"(d[3])
        : "r"(a0), "r"(a1), "r"(a2), "r"(a3), "r"(b0), "r"(b1));
}
#define CPA16(dst_u32, src_ptr) \
    asm volatile("cp.async.cg.shared.global [%0], [%1], 16;" :: "r"(dst_u32), "l"(src_ptr))

// ---------------- LayerNorm over channel dim (per pixel) ----------------
__global__ void ln_kernel(const float* __restrict__ x, const float* __restrict__ w,
                          const float* __restrict__ b, float* __restrict__ y)
{
    long p = (long)blockIdx.x * blockDim.x + threadIdx.x;
    if (p >= (long)BATCH * HWD) return;
    int bb  = (int)(p >> 16);
    int pix = (int)(p & (HWD - 1));
    const float* xp = x + (long)bb * CDIM * HWD + pix;
    float s = 0.f, s2 = 0.f;
#pragma unroll
    for (int c = 0; c < CDIM; c++) {
        float v = xp[(long)c * HWD];
        s += v; s2 += v * v;
    }
    float mu  = s * (1.0f / CDIM);
    float var = s2 * (1.0f / CDIM) - mu * mu;
    float inv = rsqrtf(var + 1e-5f);
    float* yp = y + (long)bb * CDIM * HWD + pix;
#pragma unroll
    for (int c = 0; c < CDIM; c++) {
        float v = xp[(long)c * HWD];
        yp[(long)c * HWD] = (v - mu) * inv * w[c] + b[c];
    }
}

// ---------------- row-oriented depthwise 3x3 + optional in-place row L2 normalize ------
// block = 256 threads = 4 consecutive h-rows of one (b, c); each row: 64 thr x 4 px.
// If c < normCh, the output row is divided by max(||row||, 1e-12).
__global__ void dwconv_rows_kernel(const float* __restrict__ x, const float* __restrict__ wt,
                                   const float* __restrict__ bias, float* __restrict__ y,
                                   int OC, int normCh)
{
    long bidx = blockIdx.x;
    int hb = (int)(bidx & 63) * 4;
    long bc = bidx >> 6;
    int c = (int)(bc % OC);
    int rowid = threadIdx.x >> 6;
    int t = threadIdx.x & 63;
    int h = hb + rowid;
    int w4 = t * 4;
    const float* xp = x + (bc << 16);
    float b0 = bias[c];
    float acc0 = b0, acc1 = b0, acc2 = b0, acc3 = b0;
#pragma unroll
    for (int kh = -1; kh <= 1; kh++) {
        int hh = h + kh;
        if (hh < 0 || hh >= HH) continue;
        const float* row = xp + hh * WW;
        float vm1 = (w4 > 0)      ? row[w4 - 1] : 0.f;
        float4 v  = *reinterpret_cast<const float4*>(&row[w4]);
        float vp4 = (w4 + 4 < WW) ? row[w4 + 4] : 0.f;
        float vals[6] = {vm1, v.x, v.y, v.z, v.w, vp4};
        const float* wr = wt + c * 9 + (kh + 1) * 3;
#pragma unroll
        for (int kw = 0; kw < 3; kw++) {
            float g = wr[kw];
            acc0 = fmaf(g, vals[kw + 0], acc0);
            acc1 = fmaf(g, vals[kw + 1], acc1);
            acc2 = fmaf(g, vals[kw + 2], acc2);
            acc3 = fmaf(g, vals[kw + 3], acc3);
        }
    }
    if (c < normCh) {
        float s = acc0 * acc0 + acc1 * acc1 + acc2 * acc2 + acc3 * acc3;
#pragma unroll
        for (int o = 16; o > 0; o >>= 1) s += __shfl_down_sync(0xffffffffu, s, o);
        __shared__ float part[8];
        int warp = threadIdx.x >> 5, lane = threadIdx.x & 31;
        if (lane == 0) part[warp] = s;
        __syncthreads();
        float inv = 1.f / fmaxf(sqrtf(part[rowid * 2] + part[rowid * 2 + 1]), 1e-12f);
        acc0 *= inv; acc1 *= inv; acc2 *= inv; acc3 *= inv;
    }
    *reinterpret_cast<float4*>(&y[(bc << 16) + h * WW + w4]) = make_float4(acc0, acc1, acc2, acc3);
}

// ---------------- fused FFN depthwise 3x3 + GELU gate ----------------
__global__ void dwconv_gate_kernel(const float* __restrict__ x, const float* __restrict__ wt,
                                   const float* __restrict__ bias, float* __restrict__ g)
{
    long idx = (long)blockIdx.x * blockDim.x + threadIdx.x;
    long total = (long)BATCH * HID * (HWD / 4);
    if (idx >= total) return;
    int w4 = (int)(idx & 63) * 4;
    int h  = (int)((idx >> 6) & 255);
    long bc = idx >> 14;
    int c = (int)(bc % HID);
    int b = (int)(bc / HID);
    const float* xp1 = x + ((long)b * HID2 + c) * HWD;
    const float* xp2 = xp1 + (long)HID * HWD;
    float bb1 = bias[c], bb2 = bias[c + HID];
    float a0 = bb1, a1 = bb1, a2 = bb1, a3 = bb1;
    float c0 = bb2, c1 = bb2, c2 = bb2, c3 = bb2;
    const float* w1 = wt + c * 9;
    const float* w2 = wt + (c + HID) * 9;
#pragma unroll
    for (int kh = -1; kh <= 1; kh++) {
        int hh = h + kh;
        if (hh < 0 || hh >= HH) continue;
        {
            const float* row = xp1 + hh * WW;
            float vm1 = (w4 > 0)      ? row[w4 - 1] : 0.f;
            float4 v  = *reinterpret_cast<const float4*>(&row[w4]);
            float vp4 = (w4 + 4 < WW) ? row[w4 + 4] : 0.f;
            float vals[6] = {vm1, v.x, v.y, v.z, v.w, vp4};
            const float* wr = w1 + (kh + 1) * 3;
#pragma unroll
            for (int kw = 0; kw < 3; kw++) {
                float gg = wr[kw];
                a0 = fmaf(gg, vals[kw + 0], a0);
                a1 = fmaf(gg, vals[kw + 1], a1);
                a2 = fmaf(gg, vals[kw + 2], a2);
                a3 = fmaf(gg, vals[kw + 3], a3);
            }
        }
        {
            const float* row = xp2 + hh * WW;
            float vm1 = (w4 > 0)      ? row[w4 - 1] : 0.f;
            float4 v  = *reinterpret_cast<const float4*>(&row[w4]);
            float vp4 = (w4 + 4 < WW) ? row[w4 + 4] : 0.f;
            float vals[6] = {vm1, v.x, v.y, v.z, v.w, vp4};
            const float* wr = w2 + (kh + 1) * 3;
#pragma unroll
            for (int kw = 0; kw < 3; kw++) {
                float gg = wr[kw];
                c0 = fmaf(gg, vals[kw + 0], c0);
                c1 = fmaf(gg, vals[kw + 1], c1);
                c2 = fmaf(gg, vals[kw + 2], c2);
                c3 = fmaf(gg, vals[kw + 3], c3);
            }
        }
    }
    const float k = 0.70710678118654752f;
    float4 o;
    o.x = 0.5f * a0 * (1.0f + erff(a0 * k)) * c0;
    o.y = 0.5f * a1 * (1.0f + erff(a1 * k)) * c1;
    o.z = 0.5f * a2 * (1.0f + erff(a2 * k)) * c2;
    o.w = 0.5f * a3 * (1.0f + erff(a3 * k)) * c3;
    *reinterpret_cast<float4*>(&g[((long)b * HID + c) * HWD + h * WW + w4]) = o;
}

// ---------------- hxh inverse norm: per (b,h) over (c,w) ----------------
__global__ void hnorm_kernel(const float* __restrict__ src, float* __restrict__ out)
{
    int b = blockIdx.y, h = blockIdx.x;
    int t = threadIdx.x;
    const float* p = src + (long)b * (3 * CDIM) * HWD + (long)h * WW + t;
    float s = 0.f;
#pragma unroll
    for (int c = 0; c < CDIM; c++) { float v = p[(long)c * HWD]; s += v * v; }
    __shared__ float red[256];
    red[t] = s; __syncthreads();
    for (int o = 128; o > 0; o >>= 1) { if (t < o) red[t] += red[t + o]; __syncthreads(); }
    if (t == 0) out[b * HH + h] = 1.f / fmaxf(sqrtf(red[0]), 1e-12f);
}

// ---------------- softmax over last dim of [B, 256, 256] ----------------
__global__ void softmax_kernel(float* __restrict__ attn, const float* __restrict__ temp,
                               const float* __restrict__ sq, const float* __restrict__ sk)
{
    int b = blockIdx.y;
    int r = blockIdx.x;
    float* row = attn + ((long)b * WW + r) * WW;
    int t = threadIdx.x;
    float v = row[t] * temp[0];
    if (sq) v *= sq[b * WW + r] * sk[b * WW + t];
    __shared__ float red[256];
    red[t] = v; __syncthreads();
    for (int o = 128; o > 0; o >>= 1) { if (t < o) red[t] = fmaxf(red[t], red[t + o]); __syncthreads(); }
    float mx = red[0]; __syncthreads();
    float e = __expf(v - mx);
    red[t] = e; __syncthreads();
    for (int o = 128; o > 0; o >>= 1) { if (t < o) red[t] += red[t + o]; __syncthreads(); }
    row[t] = e * (1.f / red[0]);
}

// ---------------- dedicated gram kernel: C[256,256] = Qm^T-contraction over K=16384 ----
// L=0 (wxw): operand addr = k*256 + m        (k-major, m contiguous)
// L=1 (hxh): operand addr = m*256 + (k&255) + (k>>8)*65536
// grid (2, 2, BATCH*KS); BM=BN=128, BK=16, 256 threads (2x4 warps, warp tile 64x32).
template<int L>
__global__ void __launch_bounds__(256, 2) gram_kernel(
    const float* __restrict__ Qb, const float* __restrict__ Kb,
    float* __restrict__ Cb, int KS)
{
    constexpr int P0 = 136;   // [k][m] pitch (L=0)
    constexpr int P1 = 20;    // [m][k] pitch (L=1)
    constexpr int SSZ = (L == 0) ? 2 * 16 * P0 : 2 * 128 * P1;
    __shared__ __align__(16) float As[SSZ];
    __shared__ __align__(16) float Bs[SSZ];

    int z = blockIdx.z;
    int b = z / KS, ks = z - b * KS;
    const float* Q = Qb + (long)b * (3 * CDIM * HWD);
    const float* Kp = Kb + (long)b * (3 * CDIM * HWD);
    float* C = Cb + (long)b * 65536;
    int m0 = blockIdx.x * 128, n0 = blockIdx.y * 128;
    int kchunk = 16384 / KS;          // multiple of 16
    int kbeg = ks * kchunk, kend = kbeg + kchunk;

    int tid = threadIdx.x, lane = tid & 31, warp = tid >> 5;
    int wm = warp & 1, wn = warp >> 1;          // 2 x 4
    int r = lane >> 2, c = lane & 3;

    unsigned sA = (unsigned)__cvta_generic_to_shared(As);
    unsigned sB = (unsigned)__cvta_generic_to_shared(Bs);

    auto loadStage = [&](int buf, int k0) {
        if (L == 0) {
            int row = tid >> 4;          // 0..15
            int q   = tid & 15;          // quads q, q+16
            const float* gA = Q  + (long)(k0 + row) * 256 + m0;
            const float* gB = Kp + (long)(k0 + row) * 256 + n0;
            unsigned dA = sA + ((buf * 16 + row) * P0) * 4;
            unsigned dB = sB + ((buf * 16 + row) * P0) * 4;
            CPA16(dA + q * 16,        gA + q * 4);
            CPA16(dA + (q + 16) * 16, gA + (q + 16) * 4);
            CPA16(dB + q * 16,        gB + q * 4);
            CPA16(dB + (q + 16) * 16, gB + (q + 16) * 4);
        } else {
            int m  = tid >> 1;           // 0..127
            int qi = (tid & 1) * 2;      // quads qi, qi+1
            long kb = (long)(k0 >> 8) * 65536 + (k0 & 255);
            const float* gA = Q  + (long)(m0 + m) * 256 + kb;
            const float* gB = Kp + (long)(n0 + m) * 256 + kb;
            unsigned dA = sA + ((buf * 128 + m) * P1) * 4;
            unsigned dB = sB + ((buf * 128 + m) * P1) * 4;
            CPA16(dA + qi * 16,       gA + qi * 4);
            CPA16(dA + (qi + 1) * 16, gA + (qi + 1) * 4);
            CPA16(dB + qi * 16,       gB + qi * 4);
            CPA16(dB + (qi + 1) * 16, gB + (qi + 1) * 4);
        }
    };

    float acc[16][4];
#pragma unroll
    for (int i = 0; i < 16; i++)
#pragma unroll
        for (int j = 0; j < 4; j++) acc[i][j] = 0.f;

    loadStage(0, kbeg);
    asm volatile("cp.async.commit_group;");
    int buf = 0;

    for (int k0 = kbeg; k0 < kend; k0 += 16) {
        int kn = k0 + 16;
        if (kn < kend) loadStage(buf ^ 1, kn);
        asm volatile("cp.async.commit_group;");
        asm volatile("cp.async.wait_group 1;");
        __syncthreads();

        const float* A_ = As + (L == 0 ? buf * 16 * P0 : buf * 128 * P1);
        const float* B_ = Bs + (L == 0 ? buf * 16 * P0 : buf * 128 * P1);
#pragma unroll
        for (int ks2 = 0; ks2 < 2; ks2++) {
            int kc = ks2 * 8 + c;
            unsigned a0[4], a1[4], a2[4], a3[4];
#pragma unroll
            for (int mt = 0; mt < 4; mt++) {
                int mr = wm * 64 + mt * 16 + r;
                if (L == 0) {
                    a0[mt] = __float_as_uint(A_[kc * P0 + mr]);
                    a1[mt] = __float_as_uint(A_[kc * P0 + mr + 8]);
                    a2[mt] = __float_as_uint(A_[(kc + 4) * P0 + mr]);
                    a3[mt] = __float_as_uint(A_[(kc + 4) * P0 + mr + 8]);
                } else {
                    a0[mt] = __float_as_uint(A_[mr * P1 + kc]);
                    a1[mt] = __float_as_uint(A_[(mr + 8) * P1 + kc]);
                    a2[mt] = __float_as_uint(A_[mr * P1 + kc + 4]);
                    a3[mt] = __float_as_uint(A_[(mr + 8) * P1 + kc + 4]);
                }
            }
#pragma unroll
            for (int j = 0; j < 4; j++) {
                int nn = wn * 32 + j * 8 + r;
                unsigned b0, b1;
                if (L == 0) {
                    b0 = __float_as_uint(B_[kc * P0 + nn]);
                    b1 = __float_as_uint(B_[(kc + 4) * P0 + nn]);
                } else {
                    b0 = __float_as_uint(B_[nn * P1 + kc]);
                    b1 = __float_as_uint(B_[nn * P1 + kc + 4]);
                }
#pragma unroll
                for (int mt = 0; mt < 4; mt++)
                    mma8(acc[mt * 4 + j], a0[mt], a1[mt], a2[mt], a3[mt], b0, b1);
            }
        }
        __syncthreads();
        buf ^= 1;
    }

    // ---- atomic epilogue ----
#pragma unroll
    for (int mt = 0; mt < 4; mt++) {
#pragma unroll
        for (int j = 0; j < 4; j++) {
            int mrow = m0 + wm * 64 + mt * 16 + r;
            int n    = n0 + wn * 32 + j * 8 + c * 2;
            float* ci = acc[mt * 4 + j];
            atomicAdd(&C[(long)mrow * 256 + n],           ci[0]);
            atomicAdd(&C[(long)mrow * 256 + n + 1],       ci[1]);
            atomicAdd(&C[(long)(mrow + 8) * 256 + n],     ci[2]);
            atomicAdd(&C[(long)(mrow + 8) * 256 + n + 1], ci[3]);
        }
    }
}

// ---------------- tf32 tensor-core GEMM, register-staged double buffering ----------------
template<int MT>
__global__ void __launch_bounds__(128, 3) mma_gemm(
    const float* __restrict__ A, const float* __restrict__ B, float* __restrict__ C,
    int M, int N, int K,
    long sma, long sakl, long sakh,
    long snb, long sbkl, long sbkh,
    int ldc, int ksplit, int zdiv,
    long sA1, long sA2, long sB1, long sB2, long sC1, long sC2,
    const float* __restrict__ bias,
    const float* __restrict__ res, long sR1, long sR2,
    int aCM, int bCN)
{
    const int BM = MT * 64;
    __shared__ float As[MT * 64][20];
    __shared__ float Bs[64][20];

    int z  = blockIdx.z;
    int zb = z / ksplit;
    int z1 = zb / zdiv, z2 = zb - z1 * zdiv;
    const float* Ap = A + (long)z1 * sA1 + (long)z2 * sA2;
    const float* Bp = B + (long)z1 * sB1 + (long)z2 * sB2;
    float*       Cp = C + (long)z1 * sC1 + (long)z2 * sC2;

    int m0 = blockIdx.x * BM;
    int n0 = blockIdx.y * 64;
    int kbeg = 0, kend = K;

    int tid = threadIdx.x;
    int lane = tid & 31, warp = tid >> 5;
    int r = lane >> 2, c = lane & 3;

    float ra[16];
    float rb[8];

    auto loadA = [&](int k0) {
        int krem = kend - k0;
        const float* At = Ap + (long)(k0 >> 8) * sakh + (long)(k0 & 255) * sakl;
        if (aCM) {
            if (MT == 2) {
                int mg = m0 + tid;
#pragma unroll
                for (int i = 0; i < 16; i++) {
                    float v = 0.f;
                    if (mg < M && i < krem) v = At[(long)mg * sma + (long)i * sakl];
                    ra[i] = v;
                }
            } else {
                int mg = m0 + (tid & 63), kb = (tid >> 6) * 8;
#pragma unroll
                for (int i = 0; i < 8; i++) {
                    int kk = kb + i;
                    float v = 0.f;
                    if (mg < M && kk < krem) v = At[(long)mg * sma + (long)kk * sakl];
                    ra[i] = v;
                }
            }
        } else {
#pragma unroll
            for (int i = 0; i < MT * 2; i++) {
                int q = tid + i * 128;
                int mg = m0 + (q >> 2), k4 = (q & 3) * 4;
#pragma unroll
                for (int j = 0; j < 4; j++) {
                    int kk = k4 + j;
                    float v = 0.f;
                    if (mg < M && kk < krem) v = At[(long)mg * sma + (long)kk * sakl];
                    ra[i * 4 + j] = v;
                }
            }
        }
    };

    auto loadB = [&](int k0) {
        int krem = kend - k0;
        const float* Bt = Bp + (long)(k0 >> 8) * sbkh + (long)(k0 & 255) * sbkl;
        if (bCN) {
            int ng = n0 + (tid & 63), kb = (tid >> 6) * 8;
#pragma unroll
            for (int i = 0; i < 8; i++) {
                int kk = kb + i;
                float v = 0.f;
                if (ng < N && kk < krem) v = Bt[(long)ng * snb + (long)kk * sbkl];
                rb[i] = v;
            }
        } else {
#pragma unroll
            for (int i = 0; i < 2; i++) {
                int q = tid + i * 128;
                int ng = n0 + (q >> 2), k4 = (q & 3) * 4;
#pragma unroll
                for (int j = 0; j < 4; j++) {
                    int kk = k4 + j;
                    float v = 0.f;
                    if (ng < N && kk < krem) v = Bt[(long)ng * snb + (long)kk * sbkl];
                    rb[i * 4 + j] = v;
                }
            }
        }
    };

    auto stsAB = [&]() {
        if (aCM) {
            if (MT == 2) {
#pragma unroll
                for (int i = 0; i < 4; i++)
                    *reinterpret_cast<float4*>(&As[tid][i * 4]) =
                        make_float4(tf32r(ra[i*4]), tf32r(ra[i*4+1]), tf32r(ra[i*4+2]), tf32r(ra[i*4+3]));
            } else {
                int mm = tid & 63, kb = (tid >> 6) * 8;
                *reinterpret_cast<float4*>(&As[mm][kb])     =
                    make_float4(tf32r(ra[0]), tf32r(ra[1]), tf32r(ra[2]), tf32r(ra[3]));
                *reinterpret_cast<float4*>(&As[mm][kb + 4]) =
                    make_float4(tf32r(ra[4]), tf32r(ra[5]), tf32r(ra[6]), tf32r(ra[7]));
            }
        } else {
#pragma unroll
            for (int i = 0; i < MT * 2; i++) {
                int q = tid + i * 128;
                int mm = q >> 2, k4 = (q & 3) * 4;
                *reinterpret_cast<float4*>(&As[mm][k4]) =
                    make_float4(tf32r(ra[i*4]), tf32r(ra[i*4+1]), tf32r(ra[i*4+2]), tf32r(ra[i*4+3]));
            }
        }
        if (bCN) {
            int nn = tid & 63, kb = (tid >> 6) * 8;
            *reinterpret_cast<float4*>(&Bs[nn][kb])     =
                make_float4(tf32r(rb[0]), tf32r(rb[1]), tf32r(rb[2]), tf32r(rb[3]));
            *reinterpret_cast<float4*>(&Bs[nn][kb + 4]) =
                make_float4(tf32r(rb[4]), tf32r(rb[5]), tf32r(rb[6]), tf32r(rb[7]));
        } else {
#pragma unroll
            for (int i = 0; i < 2; i++) {
                int q = tid + i * 128;
                int nn = q >> 2, k4 = (q & 3) * 4;
                *reinterpret_cast<float4*>(&Bs[nn][k4]) =
                    make_float4(tf32r(rb[i*4]), tf32r(rb[i*4+1]), tf32r(rb[i*4+2]), tf32r(rb[i*4+3]));
            }
        }
    };

    float acc[MT * 8][4];
#pragma unroll
    for (int i = 0; i < MT * 8; i++)
#pragma unroll
        for (int j = 0; j < 4; j++) acc[i][j] = 0.f;

    loadA(kbeg);
    loadB(kbeg);

    for (int k0 = kbeg; k0 < kend; k0 += 16) {
        stsAB();
        __syncthreads();
        int kn = k0 + 16;
        if (kn < kend) { loadA(kn); loadB(kn); }

#pragma unroll
        for (int ks2 = 0; ks2 < 2; ks2++) {
            int kc = ks2 * 8 + c;
            unsigned a0[MT], a1[MT], a2[MT], a3[MT];
#pragma unroll
            for (int mt = 0; mt < MT; mt++) {
                int mr = warp * (MT * 16) + mt * 16 + r;
                a0[mt] = __float_as_uint(As[mr][kc]);
                a1[mt] = __float_as_uint(As[mr + 8][kc]);
                a2[mt] = __float_as_uint(As[mr][kc + 4]);
                a3[mt] = __float_as_uint(As[mr + 8][kc + 4]);
            }
#pragma unroll
            for (int j = 0; j < 8; j++) {
                unsigned b0 = __float_as_uint(Bs[j * 8 + r][kc]);
                unsigned b1 = __float_as_uint(Bs[j * 8 + r][kc + 4]);
#pragma unroll
                for (int mt = 0; mt < MT; mt++)
                    mma8(acc[mt * 8 + j], a0[mt], a1[mt], a2[mt], a3[mt], b0, b1);
            }
        }
        __syncthreads();
    }

    const float* Rp = res ? res + (long)z1 * sR1 + (long)z2 * sR2 : nullptr;
#pragma unroll
    for (int mt = 0; mt < MT; mt++) {
#pragma unroll
        for (int j = 0; j < 8; j++) {
            int mA = m0 + warp * (MT * 16) + mt * 16 + r;
            int n  = n0 + j * 8 + c * 2;
            float* ci = acc[mt * 8 + j];
#pragma unroll
            for (int half = 0; half < 2; half++) {
                int mrow = mA + half * 8;
                if (mrow >= M || n >= N) continue;
                float bv = bias ? bias[mrow] : 0.f;
                float v0 = ci[half * 2 + 0] + bv;
                float v1 = ci[half * 2 + 1] + bv;
                long off = (long)mrow * ldc + n;
                if (Rp) { v0 += Rp[off]; v1 += Rp[off + 1]; }
                *reinterpret_cast<float2*>(&Cp[off]) = make_float2(v0, v1);
            }
        }
    }
}

// ---------------- host helper ----------------
static void mg(int MT, dim3 grid,
    const float* A, const float* B, float* C,
    int M, int N, int K,
    long sma, long sakl, long sakh,
    long snb, long sbkl, long sbkh,
    int ldc, int zdiv,
    long sA1, long sA2, long sB1, long sB2, long sC1, long sC2,
    const float* bias, const float* res, long sR1, long sR2,
    int aCM, int bCN)
{
    if (MT == 2)
        mma_gemm<2><<<grid, 128>>>(A,B,C,M,N,K,sma,sakl,sakh,snb,sbkl,sbkh,ldc,1,zdiv,
            sA1,sA2,sB1,sB2,sC1,sC2,bias,res,sR1,sR2,aCM,bCN);
    else
        mma_gemm<1><<<grid, 128>>>(A,B,C,M,N,K,sma,sakl,sakh,snb,sbkl,sbkh,ldc,1,zdiv,
            sA1,sA2,sB1,sB2,sC1,sC2,bias,res,sR1,sR2,aCM,bCN);
}

extern "C" void kernel_launch(void* const* d_in, const int* in_sizes, int n_in,
                              void* d_out, int out_size)
{
    const float* x        = (const float*)d_in[0];
    const float* w_ln_w   = (const float*)d_in[2];
    const float* w_ln_b   = (const float*)d_in[3];
    const float* w_qkv_w  = (const float*)d_in[4];
    const float* w_qkv_b  = (const float*)d_in[5];
    const float* w_dw_w   = (const float*)d_in[6];
    const float* w_dw_b   = (const float*)d_in[7];
    const float* w_proj_w = (const float*)d_in[8];
    const float* w_proj_b = (const float*)d_in[9];
    const float* w_temp   = (const float*)d_in[10];
    const float* h_ln_w   = (const float*)d_in[11];
    const float* h_ln_b   = (const float*)d_in[12];
    const float* h_qkv_w  = (const float*)d_in[13];
    const float* h_qkv_b  = (const float*)d_in[14];
    const float* h_dw_w   = (const float*)d_in[15];
    const float* h_dw_b   = (const float*)d_in[16];
    const float* h_proj_w = (const float*)d_in[17];
    const float* h_proj_b = (const float*)d_in[18];
    const float* h_temp   = (const float*)d_in[19];
    const float* n2_w     = (const float*)d_in[20];
    const float* n2_b     = (const float*)d_in[21];
    const float* ffn_in_w = (const float*)d_in[22];
    const float* ffn_in_b = (const float*)d_in[23];
    const float* ffn_dw_w = (const float*)d_in[24];
    const float* ffn_dw_b = (const float*)d_in[25];
    const float* ffn_out_w= (const float*)d_in[26];
    const float* ffn_out_b= (const float*)d_in[27];
    float* out = (float*)d_out;

    float *bufA, *bufM, *bufZ, *qkv1, *qkv2, *attn, *sq, *sk;
    cudaGetSymbolAddress((void**)&bufA, g_bufA);
    cudaGetSymbolAddress((void**)&bufM, g_bufM);
    cudaGetSymbolAddress((void**)&bufZ, g_bufZ);
    cudaGetSymbolAddress((void**)&qkv1, g_qkv1);
    cudaGetSymbolAddress((void**)&qkv2, g_qkv2);
    cudaGetSymbolAddress((void**)&attn, g_attn);
    cudaGetSymbolAddress((void**)&sq,   g_sq);
    cudaGetSymbolAddress((void**)&sk,   g_sk);

    const long sX = (long)CDIM * HWD;
    const long sQ = (long)3 * CDIM * HWD;
    const int KS = 32;

    // ================= attention (WxW) =================
    ln_kernel<<<(BATCH * HWD) / 256, 256>>>(x, w_ln_w, w_ln_b, bufA);
    mg(2, dim3(2, 1024, BATCH), w_qkv_w, bufA, qkv1, 192, HWD, 64,
       64, 1, 0,   1, HWD, 0,   HWD, 1,
       0,0, sX,0, sQ,0, w_qkv_b, nullptr,0,0, 0, 1);
    dwconv_rows_kernel<<<BATCH*192*64, 256>>>(qkv1, w_dw_w, w_dw_b, qkv2, 192, 128);
    cudaMemsetAsync(attn, 0, (size_t)BATCH * WW * WW * sizeof(float));
    gram_kernel<0><<<dim3(2, 2, BATCH * KS), 256>>>(qkv2, qkv2 + 64*(long)HWD, attn, KS);
    softmax_kernel<<<dim3(WW, BATCH), 256>>>(attn, w_temp, nullptr, nullptr);
    mg(2, dim3(128, 4, BATCH), qkv2 + 128*(long)HWD, attn, bufA, CHROWS, 256, 256,
       WW, 1, 0,   1, WW, 0,   WW, 1,
       sQ,0, (long)WW*WW,0, sX,0, nullptr, nullptr,0,0, 0, 1);
    mg(1, dim3(1, 1024, BATCH), w_proj_w, bufA, bufM, 64, HWD, 64,
       64, 1, 0,   1, HWD, 0,   HWD, 1,
       0,0, sX,0, sX,0, w_proj_b, x, sX,0, 0, 1);

    // ================= attention (HxH) =================
    ln_kernel<<<(BATCH * HWD) / 256, 256>>>(bufM, h_ln_w, h_ln_b, bufA);
    mg(2, dim3(2, 1024, BATCH), h_qkv_w, bufA, qkv1, 192, HWD, 64,
       64, 1, 0,   1, HWD, 0,   HWD, 1,
       0,0, sX,0, sQ,0, h_qkv_b, nullptr,0,0, 0, 1);
    dwconv_rows_kernel<<<BATCH*192*64, 256>>>(qkv1, h_dw_w, h_dw_b, qkv2, 192, 0);
    hnorm_kernel<<<dim3(HH, BATCH), 256>>>(qkv2,                sq);
    hnorm_kernel<<<dim3(HH, BATCH), 256>>>(qkv2 + 64*(long)HWD, sk);
    cudaMemsetAsync(attn, 0, (size_t)BATCH * WW * WW * sizeof(float));
    gram_kernel<1><<<dim3(2, 2, BATCH * KS), 256>>>(qkv2, qkv2 + 64*(long)HWD, attn, KS);
    softmax_kernel<<<dim3(WW, BATCH), 256>>>(attn, h_temp, sq, sk);
    mg(2, dim3(2, 4, BATCH*64), attn, qkv2 + 128*(long)HWD, bufA, 256, 256, 256,
       WW, 1, 0,   1, WW, 0,   WW, 64,
       (long)WW*WW,0, sQ,(long)HWD, sX,(long)HWD, nullptr, nullptr,0,0, 0, 1);
    mg(1, dim3(1, 1024, BATCH), h_proj_w, bufA, bufZ, 64, HWD, 64,
       64, 1, 0,   1, HWD, 0,   HWD, 1,
       0,0, sX,0, sX,0, h_proj_b, bufM, sX,0, 0, 1);

    // ================= FFN =================
    ln_kernel<<<(BATCH * HWD) / 256, 256>>>(bufZ, n2_w, n2_b, bufA);
    mg(2, dim3(3, 1024, BATCH), ffn_in_w, bufA, qkv1, HID2, HWD, 64,
       64, 1, 0,   1, HWD, 0,   HWD, 1,
       0,0, sX,0, (long)HID2*HWD,0, ffn_in_b, nullptr,0,0, 0, 1);
    dwconv_gate_kernel<<<((long)BATCH*HID*HWD/4 + 255)/256, 256>>>(qkv1, ffn_dw_w, ffn_dw_b, qkv2);
    mg(1, dim3(1, 1024, BATCH), ffn_out_w, qkv2, out, 64, HWD, 170,
       170, 1, 0,   1, HWD, 0,   HWD, 1,
       0,0, (long)HID*HWD,0, sX,0, ffn_out_b, bufZ, sX,0, 0, 1);
}